// round 1
// baseline (speedup 1.0000x reference)
#include <cuda_runtime.h>
#include <math.h>

#define S_LEN 2048
#define E_DIM 1024
#define H_NUM 16
#define DEPTH 64
#define BATCH 2
#define GH    (BATCH * H_NUM)   /* 32 batch-heads */
#define ROWS  (BATCH * S_LEN)   /* 4096 */

// Scratch (allocation-free rule: __device__ globals). 16 MB each.
__device__ float g_q[(size_t)GH * S_LEN * DEPTH];
__device__ float g_k[(size_t)GH * S_LEN * DEPTH];
__device__ float g_v[(size_t)GH * S_LEN * DEPTH];
__device__ float g_attn[(size_t)ROWS * E_DIM];

// ---------------------------------------------------------------------------
// GEMM + bias: C[4096x1024] = A[4096x1024] @ W[1024x1024] + bias
// mode 0/1/2: A = Aext, dst = g_q/g_k/g_v, written in head-split layout
//             [b,h,s,d] (g = b*16+h)
// mode 3:     A = g_attn, dst = dst_ext (d_out), plain row-major
// Tiling: BM=128, BN=64, BK=16; 256 threads; 8x4 microtile per thread.
// ---------------------------------------------------------------------------
__global__ void gemm_bias_kernel(const float* __restrict__ Aext,
                                 const float* __restrict__ W,
                                 const float* __restrict__ bias,
                                 float* __restrict__ dst_ext,
                                 int mode)
{
    __shared__ float As[128 * 17];   // pitch 17 to avoid bank conflicts
    __shared__ float Ws[16 * 64];

    const float* A = (mode == 3) ? g_attn : Aext;

    const int tid  = threadIdx.x;
    const int tx   = tid & 15;
    const int ty   = tid >> 4;
    const int row0 = blockIdx.y * 128;
    const int col0 = blockIdx.x * 64;

    float acc[8][4];
#pragma unroll
    for (int i = 0; i < 8; i++)
#pragma unroll
        for (int j = 0; j < 4; j++) acc[i][j] = 0.0f;

    for (int k0 = 0; k0 < E_DIM; k0 += 16) {
        // A tile 128x16 (512 float4, 2 per thread)
#pragma unroll
        for (int q = 0; q < 2; q++) {
            int idx = tid + q * 256;
            int r   = idx >> 2;
            int kk  = (idx & 3) << 2;
            float4 v = *(const float4*)(A + (size_t)(row0 + r) * E_DIM + k0 + kk);
            float* p = &As[r * 17 + kk];
            p[0] = v.x; p[1] = v.y; p[2] = v.z; p[3] = v.w;
        }
        // W tile 16x64 (256 float4, 1 per thread)
        {
            int kk = tid >> 4;
            int c  = (tid & 15) << 2;
            float4 v = *(const float4*)(W + (size_t)(k0 + kk) * E_DIM + col0 + c);
            *(float4*)&Ws[kk * 64 + c] = v;
        }
        __syncthreads();

#pragma unroll
        for (int kk = 0; kk < 16; kk++) {
            float a[8];
#pragma unroll
            for (int i = 0; i < 8; i++) a[i] = As[(ty * 8 + i) * 17 + kk];
            float4 bv = *(float4*)&Ws[kk * 64 + tx * 4];
            float b[4] = {bv.x, bv.y, bv.z, bv.w};
#pragma unroll
            for (int i = 0; i < 8; i++)
#pragma unroll
                for (int j = 0; j < 4; j++)
                    acc[i][j] = fmaf(a[i], b[j], acc[i][j]);
        }
        __syncthreads();
    }

    float* dst;
    if      (mode == 0) dst = g_q;
    else if (mode == 1) dst = g_k;
    else if (mode == 2) dst = g_v;
    else                dst = dst_ext;
    const bool head_split = (mode < 3);

#pragma unroll
    for (int i = 0; i < 8; i++) {
        int r = row0 + ty * 8 + i;
#pragma unroll
        for (int j = 0; j < 4; j++) {
            int c = col0 + tx * 4 + j;
            float v = acc[i][j] + bias[c];
            if (head_split) {
                int b = r >> 11, s = r & 2047;
                int h = c >> 6,  d = c & 63;
                dst[(((size_t)(b * H_NUM + h) * S_LEN + s) << 6) + d] = v;
            } else {
                dst[(size_t)r * E_DIM + c] = v;
            }
        }
    }
}

// ---------------------------------------------------------------------------
// scores[g][i][j] = dot(V_g[i], K_g[j]) / 8, written raw into probs region.
// 64x64 output tile per block, 128 threads, 4x8 microtile.
// ---------------------------------------------------------------------------
__global__ void scores_kernel(float* __restrict__ probs)
{
    __shared__ float Vs[64 * 65];
    __shared__ float Ks[64 * 65];

    const int g  = blockIdx.z;
    const float* Vg = g_v + (size_t)g * S_LEN * DEPTH;
    const float* Kg = g_k + (size_t)g * S_LEN * DEPTH;
    float* Pg = probs + (size_t)g * S_LEN * S_LEN;

    const int i0  = blockIdx.y * 64;
    const int j0  = blockIdx.x * 64;
    const int tid = threadIdx.x;       // 128
    const int tx  = tid & 7;
    const int ty  = tid >> 3;

    // Load both 64x64 tiles (1024 float4 each / 128 threads = 8 each)
#pragma unroll
    for (int q = 0; q < 8; q++) {
        int idx = tid + q * 128;
        int r   = idx >> 4;
        int d   = (idx & 15) << 2;
        float4 v = *(const float4*)(Vg + ((size_t)(i0 + r) << 6) + d);
        float* pv = &Vs[r * 65 + d];
        pv[0] = v.x; pv[1] = v.y; pv[2] = v.z; pv[3] = v.w;
        float4 k = *(const float4*)(Kg + ((size_t)(j0 + r) << 6) + d);
        float* pk = &Ks[r * 65 + d];
        pk[0] = k.x; pk[1] = k.y; pk[2] = k.z; pk[3] = k.w;
    }
    __syncthreads();

    float acc[4][8];
#pragma unroll
    for (int i = 0; i < 4; i++)
#pragma unroll
        for (int j = 0; j < 8; j++) acc[i][j] = 0.0f;

#pragma unroll 8
    for (int d = 0; d < 64; d++) {
        float a[4], b[8];
#pragma unroll
        for (int i = 0; i < 4; i++) a[i] = Vs[(ty * 4 + i) * 65 + d];
#pragma unroll
        for (int j = 0; j < 8; j++) b[j] = Ks[(tx * 8 + j) * 65 + d];
#pragma unroll
        for (int i = 0; i < 4; i++)
#pragma unroll
            for (int j = 0; j < 8; j++)
                acc[i][j] = fmaf(a[i], b[j], acc[i][j]);
    }

    const float scale = 0.125f;  // 1/sqrt(64)
#pragma unroll
    for (int i = 0; i < 4; i++) {
        size_t base = (size_t)(i0 + ty * 4 + i) * S_LEN + j0 + tx * 8;
        float4 o0, o1;
        o0.x = acc[i][0] * scale; o0.y = acc[i][1] * scale;
        o0.z = acc[i][2] * scale; o0.w = acc[i][3] * scale;
        o1.x = acc[i][4] * scale; o1.y = acc[i][5] * scale;
        o1.z = acc[i][6] * scale; o1.w = acc[i][7] * scale;
        *(float4*)(Pg + base)     = o0;
        *(float4*)(Pg + base + 4) = o1;
    }
}

// ---------------------------------------------------------------------------
// In-place row softmax over 2048 columns. One block (256 threads) per row.
// ---------------------------------------------------------------------------
__global__ void softmax_kernel(float* __restrict__ probs)
{
    float* row = probs + (size_t)blockIdx.x * S_LEN;
    const int tid = threadIdx.x;
    __shared__ float red[8];

    float x[8];
#pragma unroll
    for (int q = 0; q < 8; q++) x[q] = row[tid + q * 256];

    // block max
    float m = x[0];
#pragma unroll
    for (int q = 1; q < 8; q++) m = fmaxf(m, x[q]);
#pragma unroll
    for (int o = 16; o > 0; o >>= 1)
        m = fmaxf(m, __shfl_xor_sync(0xffffffffu, m, o));
    if ((tid & 31) == 0) red[tid >> 5] = m;
    __syncthreads();
    if (tid < 8) {
        float v = red[tid];
#pragma unroll
        for (int o = 4; o > 0; o >>= 1)
            v = fmaxf(v, __shfl_xor_sync(0xffu, v, o));
        if (tid == 0) red[0] = v;
    }
    __syncthreads();
    m = red[0];
    __syncthreads();

    // exp + block sum
    float s = 0.0f;
#pragma unroll
    for (int q = 0; q < 8; q++) {
        x[q] = expf(x[q] - m);
        s += x[q];
    }
#pragma unroll
    for (int o = 16; o > 0; o >>= 1)
        s += __shfl_xor_sync(0xffffffffu, s, o);
    if ((tid & 31) == 0) red[tid >> 5] = s;
    __syncthreads();
    if (tid < 8) {
        float v = red[tid];
#pragma unroll
        for (int o = 4; o > 0; o >>= 1)
            v += __shfl_xor_sync(0xffu, v, o);
        if (tid == 0) red[0] = v;
    }
    __syncthreads();
    const float inv = 1.0f / red[0];

#pragma unroll
    for (int q = 0; q < 8; q++) row[tid + q * 256] = x[q] * inv;
}

// ---------------------------------------------------------------------------
// attn_g[i][d] = sum_j probs_g[i][j] * Q_g[j][d]; written to g_attn in
// [b, s, h*64+d] layout. Block: 64 rows x 64 (full depth), 128 threads,
// 4x8 microtile, BK=32.
// ---------------------------------------------------------------------------
__global__ void attn_kernel(const float* __restrict__ probs)
{
    __shared__ float Ps[64 * 33];
    __shared__ float Qs[32 * 64];

    const int g  = blockIdx.y;
    const float* Pg = probs + (size_t)g * S_LEN * S_LEN;
    const float* Qg = g_q + (size_t)g * S_LEN * DEPTH;

    const int i0  = blockIdx.x * 64;
    const int tid = threadIdx.x;       // 128
    const int tx  = tid & 7;
    const int ty  = tid >> 3;

    float acc[4][8];
#pragma unroll
    for (int i = 0; i < 4; i++)
#pragma unroll
        for (int j = 0; j < 8; j++) acc[i][j] = 0.0f;

    for (int k0 = 0; k0 < S_LEN; k0 += 32) {
        // P tile 64x32 (512 float4 / 128 threads = 4 each)
#pragma unroll
        for (int q = 0; q < 4; q++) {
            int idx = tid + q * 128;
            int r   = idx >> 3;
            int kk  = (idx & 7) << 2;
            float4 v = *(const float4*)(Pg + (size_t)(i0 + r) * S_LEN + k0 + kk);
            float* p = &Ps[r * 33 + kk];
            p[0] = v.x; p[1] = v.y; p[2] = v.z; p[3] = v.w;
        }
        // Q tile 32x64 (512 float4 / 128 threads = 4 each)
#pragma unroll
        for (int q = 0; q < 4; q++) {
            int idx = tid + q * 128;
            int kk  = idx >> 4;
            int d   = (idx & 15) << 2;
            float4 v = *(const float4*)(Qg + ((size_t)(k0 + kk) << 6) + d);
            *(float4*)&Qs[kk * 64 + d] = v;
        }
        __syncthreads();

#pragma unroll
        for (int kk = 0; kk < 32; kk++) {
            float a[4];
#pragma unroll
            for (int i = 0; i < 4; i++) a[i] = Ps[(ty * 4 + i) * 33 + kk];
            float4 b0 = *(float4*)&Qs[kk * 64 + tx * 8];
            float4 b1 = *(float4*)&Qs[kk * 64 + tx * 8 + 4];
            float b[8] = {b0.x, b0.y, b0.z, b0.w, b1.x, b1.y, b1.z, b1.w};
#pragma unroll
            for (int i = 0; i < 4; i++)
#pragma unroll
                for (int j = 0; j < 8; j++)
                    acc[i][j] = fmaf(a[i], b[j], acc[i][j]);
        }
        __syncthreads();
    }

    const int b = g >> 4;
    const int h = g & 15;
#pragma unroll
    for (int i = 0; i < 4; i++) {
        size_t base = (size_t)(b * S_LEN + i0 + ty * 4 + i) * E_DIM + h * 64 + tx * 8;
        float4 o0, o1;
        o0.x = acc[i][0]; o0.y = acc[i][1]; o0.z = acc[i][2]; o0.w = acc[i][3];
        o1.x = acc[i][4]; o1.y = acc[i][5]; o1.z = acc[i][6]; o1.w = acc[i][7];
        *(float4*)(g_attn + base)     = o0;
        *(float4*)(g_attn + base + 4) = o1;
    }
}

// ---------------------------------------------------------------------------
extern "C" void kernel_launch(void* const* d_in, const int* in_sizes, int n_in,
                              void* d_out, int out_size)
{
    const float* query = (const float*)d_in[0];
    const float* key   = (const float*)d_in[1];
    const float* value = (const float*)d_in[2];
    const float* wq    = (const float*)d_in[3];
    const float* bq    = (const float*)d_in[4];
    const float* wk    = (const float*)d_in[5];
    const float* bk    = (const float*)d_in[6];
    const float* wv    = (const float*)d_in[7];
    const float* bv    = (const float*)d_in[8];
    const float* wf    = (const float*)d_in[9];
    const float* bf    = (const float*)d_in[10];

    float* out = (float*)d_out;
    // Output is (out, probs) concatenated: probs sits at the tail.
    const size_t probs_elems = (size_t)GH * S_LEN * S_LEN;   // 134217728
    size_t off = ((size_t)out_size > probs_elems) ? ((size_t)out_size - probs_elems) : 0;
    float* probs = out + off;

    dim3 gemm_grid(E_DIM / 64, ROWS / 128);   // (16, 32)
    gemm_bias_kernel<<<gemm_grid, 256>>>(query, wq, bq, nullptr, 0);  // -> g_q
    gemm_bias_kernel<<<gemm_grid, 256>>>(key,   wk, bk, nullptr, 1);  // -> g_k
    gemm_bias_kernel<<<gemm_grid, 256>>>(value, wv, bv, nullptr, 2);  // -> g_v

    scores_kernel<<<dim3(S_LEN / 64, S_LEN / 64, GH), 128>>>(probs);
    softmax_kernel<<<GH * S_LEN, 256>>>(probs);
    attn_kernel<<<dim3(S_LEN / 64, GH), 128>>>(probs);

    gemm_bias_kernel<<<gemm_grid, 256>>>(nullptr, wf, bf, out, 3);    // g_attn -> out
}

// round 2
// speedup vs baseline: 1.2823x; 1.2823x over previous
#include <cuda_runtime.h>

#define S_LEN 2048
#define E_DIM 1024
#define H_NUM 16
#define DEPTH 64
#define BATCH 2
#define GH    (BATCH * H_NUM)   /* 32 batch-heads */
#define ROWS  (BATCH * S_LEN)   /* 4096 */

// Scratch (allocation-free rule: __device__ globals). 16 MB each.
__device__ float g_q[(size_t)GH * S_LEN * DEPTH];
__device__ float g_k[(size_t)GH * S_LEN * DEPTH];
__device__ float g_v[(size_t)GH * S_LEN * DEPTH];
__device__ float g_attn[(size_t)ROWS * E_DIM];

// ---------------------------------------------------------------------------
// Common GEMM body: C[4096x1024] = A @ W + bias, BM=BN=128, BK=16,
// 256 threads, 8x8 microtile, A stored transposed in smem so the inner loop
// is 4x LDS.128 per 64 FMAs.
// ---------------------------------------------------------------------------
template<bool HEAD_SPLIT>
__device__ __forceinline__ void gemm_body(const float* __restrict__ A,
                                          const float* __restrict__ W,
                                          const float* __restrict__ bias,
                                          float* __restrict__ dst)
{
    __shared__ float As[16][132];   // [k][m], pitch 132 (528B = 33*16, keeps 16B align)
    __shared__ float Ws[16][128];   // [k][n]

    const int tid  = threadIdx.x;
    const int tx   = tid & 15;      // 16 col-groups of 8
    const int ty   = tid >> 4;      // 16 row-groups of 8
    const int row0 = blockIdx.y * 128;
    const int col0 = blockIdx.x * 128;

    float acc[8][8];
#pragma unroll
    for (int i = 0; i < 8; i++)
#pragma unroll
        for (int j = 0; j < 8; j++) acc[i][j] = 0.0f;

    for (int k0 = 0; k0 < E_DIM; k0 += 16) {
        // A tile 128x16 -> transposed into As (512 float4, 2/thread)
#pragma unroll
        for (int q = 0; q < 2; q++) {
            int idx = tid + q * 256;
            int r   = idx >> 2;
            int kk  = (idx & 3) << 2;
            float4 v = *(const float4*)(A + (size_t)(row0 + r) * E_DIM + k0 + kk);
            As[kk + 0][r] = v.x; As[kk + 1][r] = v.y;
            As[kk + 2][r] = v.z; As[kk + 3][r] = v.w;
        }
        // W tile 16x128 (512 float4, 2/thread, coalesced)
#pragma unroll
        for (int q = 0; q < 2; q++) {
            int idx = tid + q * 256;
            int kk  = idx >> 5;
            int c   = (idx & 31) << 2;
            *(float4*)&Ws[kk][c] =
                *(const float4*)(W + (size_t)(k0 + kk) * E_DIM + col0 + c);
        }
        __syncthreads();

#pragma unroll
        for (int kk = 0; kk < 16; kk++) {
            float4 a0 = *(float4*)&As[kk][ty * 8];
            float4 a1 = *(float4*)&As[kk][ty * 8 + 4];
            float4 b0 = *(float4*)&Ws[kk][tx * 8];
            float4 b1 = *(float4*)&Ws[kk][tx * 8 + 4];
            float a[8] = {a0.x, a0.y, a0.z, a0.w, a1.x, a1.y, a1.z, a1.w};
            float b[8] = {b0.x, b0.y, b0.z, b0.w, b1.x, b1.y, b1.z, b1.w};
#pragma unroll
            for (int i = 0; i < 8; i++)
#pragma unroll
                for (int j = 0; j < 8; j++)
                    acc[i][j] = fmaf(a[i], b[j], acc[i][j]);
        }
        __syncthreads();
    }

#pragma unroll
    for (int i = 0; i < 8; i++) {
        int r = row0 + ty * 8 + i;
#pragma unroll
        for (int jq = 0; jq < 2; jq++) {
            int c = col0 + tx * 8 + jq * 4;
            float4 o;
            o.x = acc[i][jq * 4 + 0] + bias[c + 0];
            o.y = acc[i][jq * 4 + 1] + bias[c + 1];
            o.z = acc[i][jq * 4 + 2] + bias[c + 2];
            o.w = acc[i][jq * 4 + 3] + bias[c + 3];
            if (HEAD_SPLIT) {
                int b = r >> 11, s = r & 2047;
                int h = c >> 6,  d = c & 63;     // float4 never crosses a head (c%64<=60)
                *(float4*)&dst[(((size_t)(b * H_NUM + h) * S_LEN + s) << 6) + d] = o;
            } else {
                *(float4*)&dst[(size_t)r * E_DIM + c] = o;
            }
        }
    }
}

__global__ void __launch_bounds__(256)
qkv_gemm_kernel(const float* __restrict__ q, const float* __restrict__ k,
                const float* __restrict__ v,
                const float* __restrict__ wq, const float* __restrict__ bq,
                const float* __restrict__ wk, const float* __restrict__ bk,
                const float* __restrict__ wv, const float* __restrict__ bv)
{
    const float *A, *W, *B;
    float* dst;
    if      (blockIdx.z == 0) { A = q; W = wq; B = bq; dst = g_q; }
    else if (blockIdx.z == 1) { A = k; W = wk; B = bk; dst = g_k; }
    else                      { A = v; W = wv; B = bv; dst = g_v; }
    gemm_body<true>(A, W, B, dst);
}

__global__ void __launch_bounds__(256)
final_gemm_kernel(const float* __restrict__ wf, const float* __restrict__ bf,
                  float* __restrict__ out)
{
    gemm_body<false>(g_attn, wf, bf, out);
}

// ---------------------------------------------------------------------------
// scores[g][i][j] = dot(V_g[i], K_g[j]) / 8. 128x128 tile, 256 threads,
// 8x8 microtile, both operands transposed in smem, K staged in 2x32 chunks.
// ---------------------------------------------------------------------------
__global__ void __launch_bounds__(256)
scores_kernel(float* __restrict__ probs)
{
    __shared__ float Vs[32][132];   // [d][i]
    __shared__ float Ks[32][132];   // [d][j]

    const int g  = blockIdx.z;
    const float* Vg = g_v + (size_t)g * S_LEN * DEPTH;
    const float* Kg = g_k + (size_t)g * S_LEN * DEPTH;
    float* Pg = probs + (size_t)g * S_LEN * S_LEN;

    const int i0  = blockIdx.y * 128;
    const int j0  = blockIdx.x * 128;
    const int tid = threadIdx.x;
    const int tx  = tid & 15;
    const int ty  = tid >> 4;

    float acc[8][8];
#pragma unroll
    for (int i = 0; i < 8; i++)
#pragma unroll
        for (int j = 0; j < 8; j++) acc[i][j] = 0.0f;

    for (int k0 = 0; k0 < DEPTH; k0 += 32) {
        // 128x32 of V and K, transposed into smem (4 float4 each / thread)
#pragma unroll
        for (int q = 0; q < 4; q++) {
            int idx = tid + q * 256;
            int r   = idx >> 3;
            int d4  = (idx & 7) << 2;
            float4 a = *(const float4*)(Vg + ((size_t)(i0 + r) << 6) + k0 + d4);
            Vs[d4 + 0][r] = a.x; Vs[d4 + 1][r] = a.y;
            Vs[d4 + 2][r] = a.z; Vs[d4 + 3][r] = a.w;
            float4 b = *(const float4*)(Kg + ((size_t)(j0 + r) << 6) + k0 + d4);
            Ks[d4 + 0][r] = b.x; Ks[d4 + 1][r] = b.y;
            Ks[d4 + 2][r] = b.z; Ks[d4 + 3][r] = b.w;
        }
        __syncthreads();

#pragma unroll
        for (int kk = 0; kk < 32; kk++) {
            float4 a0 = *(float4*)&Vs[kk][ty * 8];
            float4 a1 = *(float4*)&Vs[kk][ty * 8 + 4];
            float4 b0 = *(float4*)&Ks[kk][tx * 8];
            float4 b1 = *(float4*)&Ks[kk][tx * 8 + 4];
            float a[8] = {a0.x, a0.y, a0.z, a0.w, a1.x, a1.y, a1.z, a1.w};
            float b[8] = {b0.x, b0.y, b0.z, b0.w, b1.x, b1.y, b1.z, b1.w};
#pragma unroll
            for (int i = 0; i < 8; i++)
#pragma unroll
                for (int j = 0; j < 8; j++)
                    acc[i][j] = fmaf(a[i], b[j], acc[i][j]);
        }
        __syncthreads();
    }

    const float scale = 0.125f;   // 1/sqrt(64)
#pragma unroll
    for (int i = 0; i < 8; i++) {
        size_t base = (size_t)(i0 + ty * 8 + i) * S_LEN + j0 + tx * 8;
#pragma unroll
        for (int jq = 0; jq < 2; jq++) {
            float4 o;
            o.x = acc[i][jq * 4 + 0] * scale;
            o.y = acc[i][jq * 4 + 1] * scale;
            o.z = acc[i][jq * 4 + 2] * scale;
            o.w = acc[i][jq * 4 + 3] * scale;
            *(float4*)(Pg + base + jq * 4) = o;
        }
    }
}

// ---------------------------------------------------------------------------
// In-place row softmax over 2048 cols. One block (256 threads) per row.
// ---------------------------------------------------------------------------
__global__ void __launch_bounds__(256)
softmax_kernel(float* __restrict__ probs)
{
    float* row = probs + (size_t)blockIdx.x * S_LEN;
    const int tid = threadIdx.x;
    __shared__ float red[8];

    float4 x0 = *(float4*)(row + tid * 4);
    float4 x1 = *(float4*)(row + tid * 4 + 1024);
    float x[8] = {x0.x, x0.y, x0.z, x0.w, x1.x, x1.y, x1.z, x1.w};

    float m = x[0];
#pragma unroll
    for (int q = 1; q < 8; q++) m = fmaxf(m, x[q]);
#pragma unroll
    for (int o = 16; o > 0; o >>= 1)
        m = fmaxf(m, __shfl_xor_sync(0xffffffffu, m, o));
    if ((tid & 31) == 0) red[tid >> 5] = m;
    __syncthreads();
    if (tid < 8) {
        float v = red[tid];
#pragma unroll
        for (int o = 4; o > 0; o >>= 1)
            v = fmaxf(v, __shfl_xor_sync(0xffu, v, o));
        if (tid == 0) red[0] = v;
    }
    __syncthreads();
    m = red[0];
    __syncthreads();

    float s = 0.0f;
#pragma unroll
    for (int q = 0; q < 8; q++) {
        x[q] = __expf(x[q] - m);
        s += x[q];
    }
#pragma unroll
    for (int o = 16; o > 0; o >>= 1)
        s += __shfl_xor_sync(0xffffffffu, s, o);
    if ((tid & 31) == 0) red[tid >> 5] = s;
    __syncthreads();
    if (tid < 8) {
        float v = red[tid];
#pragma unroll
        for (int o = 4; o > 0; o >>= 1)
            v += __shfl_xor_sync(0xffu, v, o);
        if (tid == 0) red[0] = v;
    }
    __syncthreads();
    const float inv = 1.0f / red[0];

    float4 y0 = {x[0] * inv, x[1] * inv, x[2] * inv, x[3] * inv};
    float4 y1 = {x[4] * inv, x[5] * inv, x[6] * inv, x[7] * inv};
    *(float4*)(row + tid * 4)        = y0;
    *(float4*)(row + tid * 4 + 1024) = y1;
}

// ---------------------------------------------------------------------------
// attn_g[i][d] = sum_j probs_g[i][j] * Q_g[j][d], written to g_attn in
// [b, s, h*64+d] layout. 128 rows x 64 cols per block, 256 threads,
// 8x4 microtile, BK=32, P transposed in smem.
// ---------------------------------------------------------------------------
__global__ void __launch_bounds__(256)
attn_kernel(const float* __restrict__ probs)
{
    __shared__ float Ps[32][132];   // [k][i]
    __shared__ float Qs[32][64];    // [k][d]

    const int g  = blockIdx.y;
    const float* Pg = probs + (size_t)g * S_LEN * S_LEN;
    const float* Qg = g_q + (size_t)g * S_LEN * DEPTH;

    const int i0  = blockIdx.x * 128;
    const int tid = threadIdx.x;
    const int tx  = tid & 15;   // 16 col-groups of 4
    const int ty  = tid >> 4;   // 16 row-groups of 8

    float acc[8][4];
#pragma unroll
    for (int i = 0; i < 8; i++)
#pragma unroll
        for (int j = 0; j < 4; j++) acc[i][j] = 0.0f;

    for (int k0 = 0; k0 < S_LEN; k0 += 32) {
        // P tile 128x32 -> transposed (4 float4 / thread)
#pragma unroll
        for (int q = 0; q < 4; q++) {
            int idx = tid + q * 256;
            int r   = idx >> 3;
            int kk  = (idx & 7) << 2;
            float4 v = *(const float4*)(Pg + (size_t)(i0 + r) * S_LEN + k0 + kk);
            Ps[kk + 0][r] = v.x; Ps[kk + 1][r] = v.y;
            Ps[kk + 2][r] = v.z; Ps[kk + 3][r] = v.w;
        }
        // Q tile 32x64 (2 float4 / thread)
#pragma unroll
        for (int q = 0; q < 2; q++) {
            int idx = tid + q * 256;
            int kk  = idx >> 4;
            int d   = (idx & 15) << 2;
            *(float4*)&Qs[kk][d] =
                *(const float4*)(Qg + ((size_t)(k0 + kk) << 6) + d);
        }
        __syncthreads();

#pragma unroll
        for (int kk = 0; kk < 32; kk++) {
            float4 a0 = *(float4*)&Ps[kk][ty * 8];
            float4 a1 = *(float4*)&Ps[kk][ty * 8 + 4];
            float4 b0 = *(float4*)&Qs[kk][tx * 4];
            float a[8] = {a0.x, a0.y, a0.z, a0.w, a1.x, a1.y, a1.z, a1.w};
            float b[4] = {b0.x, b0.y, b0.z, b0.w};
#pragma unroll
            for (int i = 0; i < 8; i++)
#pragma unroll
                for (int j = 0; j < 4; j++)
                    acc[i][j] = fmaf(a[i], b[j], acc[i][j]);
        }
        __syncthreads();
    }

    const int b = g >> 4;
    const int h = g & 15;
#pragma unroll
    for (int i = 0; i < 8; i++) {
        size_t base = (size_t)(b * S_LEN + i0 + ty * 8 + i) * E_DIM + h * 64 + tx * 4;
        float4 o = {acc[i][0], acc[i][1], acc[i][2], acc[i][3]};
        *(float4*)&g_attn[base] = o;
    }
}

// ---------------------------------------------------------------------------
extern "C" void kernel_launch(void* const* d_in, const int* in_sizes, int n_in,
                              void* d_out, int out_size)
{
    const float* query = (const float*)d_in[0];
    const float* key   = (const float*)d_in[1];
    const float* value = (const float*)d_in[2];
    const float* wq    = (const float*)d_in[3];
    const float* bq    = (const float*)d_in[4];
    const float* wk    = (const float*)d_in[5];
    const float* bk    = (const float*)d_in[6];
    const float* wv    = (const float*)d_in[7];
    const float* bv    = (const float*)d_in[8];
    const float* wf    = (const float*)d_in[9];
    const float* bf    = (const float*)d_in[10];

    float* out = (float*)d_out;
    const size_t probs_elems = (size_t)GH * S_LEN * S_LEN;   // 134217728
    size_t off = ((size_t)out_size > probs_elems) ? ((size_t)out_size - probs_elems) : 0;
    float* probs = out + off;

    qkv_gemm_kernel<<<dim3(E_DIM / 128, ROWS / 128, 3), 256>>>(
        query, key, value, wq, bq, wk, bk, wv, bv);

    scores_kernel<<<dim3(S_LEN / 128, S_LEN / 128, GH), 256>>>(probs);
    softmax_kernel<<<GH * S_LEN, 256>>>(probs);
    attn_kernel<<<dim3(S_LEN / 128, GH), 256>>>(probs);

    final_gemm_kernel<<<dim3(E_DIM / 128, ROWS / 128), 256>>>(wf, bf, out);
}

// round 4
// speedup vs baseline: 2.4733x; 1.9287x over previous
#include <cuda_runtime.h>
#include <cuda_bf16.h>
#include <cstdint>

#define S_LEN 2048
#define E_DIM 1024
#define H_NUM 16
#define DEPTH 64
#define BATCH 2
#define GH    (BATCH * H_NUM)
#define ROWS  (BATCH * S_LEN)

// ---------------------------------------------------------------------------
// Device scratch (allocation-free rule)
// ---------------------------------------------------------------------------
__device__ __nv_bfloat16 g_wth[4u * 1024 * 1024];          // W^T hi [mode][n][k]
__device__ __nv_bfloat16 g_wtl[4u * 1024 * 1024];          // W^T lo
__device__ __nv_bfloat16 g_qh[(size_t)GH * S_LEN * DEPTH]; // Q proj [g][s][d]
__device__ __nv_bfloat16 g_ql[(size_t)GH * S_LEN * DEPTH];
__device__ __nv_bfloat16 g_kh[(size_t)GH * S_LEN * DEPTH];
__device__ __nv_bfloat16 g_kl[(size_t)GH * S_LEN * DEPTH];
__device__ __nv_bfloat16 g_vh[(size_t)GH * S_LEN * DEPTH];
__device__ __nv_bfloat16 g_vl[(size_t)GH * S_LEN * DEPTH];
__device__ __nv_bfloat16 g_ah[(size_t)ROWS * E_DIM];       // attn out [row][col]
__device__ __nv_bfloat16 g_al[(size_t)ROWS * E_DIM];

// ---------------------------------------------------------------------------
// Helpers (baseline PTX only: ldmatrix + mma.sync, sm_80-compatible)
// ---------------------------------------------------------------------------
__device__ __forceinline__ uint32_t smem_u32(const void* p) {
    uint32_t a;
    asm("{ .reg .u64 t; cvta.to.shared.u64 t, %1; cvt.u32.u64 %0, t; }"
        : "=r"(a) : "l"(p));
    return a;
}
__device__ __forceinline__ void ldsm4(uint32_t* r, uint32_t a) {
    asm volatile("ldmatrix.sync.aligned.m8n8.x4.shared.b16 {%0,%1,%2,%3}, [%4];"
                 : "=r"(r[0]), "=r"(r[1]), "=r"(r[2]), "=r"(r[3]) : "r"(a));
}
__device__ __forceinline__ void ldsm4t(uint32_t* r, uint32_t a) {
    asm volatile("ldmatrix.sync.aligned.m8n8.x4.trans.shared.b16 {%0,%1,%2,%3}, [%4];"
                 : "=r"(r[0]), "=r"(r[1]), "=r"(r[2]), "=r"(r[3]) : "r"(a));
}
__device__ __forceinline__ void mma16816(float* d, const uint32_t* a, const uint32_t* b) {
    asm volatile("mma.sync.aligned.m16n8k16.row.col.f32.bf16.bf16.f32 "
                 "{%0,%1,%2,%3}, {%4,%5,%6,%7}, {%8,%9}, {%0,%1,%2,%3};"
                 : "+f"(d[0]), "+f"(d[1]), "+f"(d[2]), "+f"(d[3])
                 : "r"(a[0]), "r"(a[1]), "r"(a[2]), "r"(a[3]), "r"(b[0]), "r"(b[1]));
}
__device__ __forceinline__ uint32_t pack_bf2(__nv_bfloat16 a, __nv_bfloat16 b) {
    return ((uint32_t)__bfloat16_as_ushort(b) << 16) | (uint32_t)__bfloat16_as_ushort(a);
}
__device__ __forceinline__ void split2(float x, float y, uint32_t& h, uint32_t& l) {
    __nv_bfloat16 hx = __float2bfloat16(x), hy = __float2bfloat16(y);
    h = pack_bf2(hx, hy);
    l = pack_bf2(__float2bfloat16(x - __bfloat162float(hx)),
                 __float2bfloat16(y - __bfloat162float(hy)));
}

// 128x128 CTA tile mma step: warp (wm,wn) computes 64x32; KSTEPS k16 steps.
// 3-term split: Ah*Bh + Ah*Bl + Al*Bh, fp32 accumulate.
template<int KSTEPS, int AP, int BP>
__device__ __forceinline__ void mma_block128(float (&acc)[4][4][4],
    uint32_t sAh, uint32_t sAl, uint32_t sBh, uint32_t sBl,
    int lane, int wm, int wn)
{
#pragma unroll
    for (int ks = 0; ks < KSTEPS; ks++) {
        uint32_t ah[4][4], al[4][4], bh[4][2], bl[4][2];
        const int arow = wm * 64 + (lane & 15);
        const int acol = ks * 16 + ((lane & 16) >> 1);
#pragma unroll
        for (int mt = 0; mt < 4; mt++) {
            uint32_t off = (uint32_t)(((arow + mt * 16) * AP + acol) << 1);
            ldsm4(ah[mt], sAh + off);
            ldsm4(al[mt], sAl + off);
        }
        const int brow = wn * 32 + (lane & 7) + ((lane & 16) >> 1);
        const int bcol = ks * 16 + (lane & 8);
#pragma unroll
        for (int p = 0; p < 2; p++) {
            uint32_t off = (uint32_t)(((brow + p * 16) * BP + bcol) << 1);
            uint32_t t4[4];
            ldsm4(t4, sBh + off);
            bh[p*2][0] = t4[0]; bh[p*2][1] = t4[1];
            bh[p*2+1][0] = t4[2]; bh[p*2+1][1] = t4[3];
            ldsm4(t4, sBl + off);
            bl[p*2][0] = t4[0]; bl[p*2][1] = t4[1];
            bl[p*2+1][0] = t4[2]; bl[p*2+1][1] = t4[3];
        }
#pragma unroll
        for (int mt = 0; mt < 4; mt++)
#pragma unroll
            for (int nt = 0; nt < 4; nt++) {
                mma16816(acc[mt][nt], ah[mt], bh[nt]);
                mma16816(acc[mt][nt], ah[mt], bl[nt]);
                mma16816(acc[mt][nt], al[mt], bh[nt]);
            }
    }
}

// ---------------------------------------------------------------------------
// Pre-pass: transpose + split the 4 weight matrices
// ---------------------------------------------------------------------------
__global__ void prep_w_kernel(const float* __restrict__ wq, const float* __restrict__ wk,
                              const float* __restrict__ wv, const float* __restrict__ wf)
{
    __shared__ float t[32][33];
    const float* W = (blockIdx.z == 0) ? wq : (blockIdx.z == 1) ? wk
                   : (blockIdx.z == 2) ? wv : wf;
    __nv_bfloat16* dh = g_wth + ((size_t)blockIdx.z << 20);
    __nv_bfloat16* dl = g_wtl + ((size_t)blockIdx.z << 20);
    int k0 = blockIdx.y * 32, n0 = blockIdx.x * 32;
    int tx = threadIdx.x, ty = threadIdx.y;
    for (int r = ty; r < 32; r += 8)
        t[r][tx] = W[(size_t)(k0 + r) * E_DIM + n0 + tx];
    __syncthreads();
    for (int r = ty; r < 32; r += 8) {
        float v = t[tx][r];
        __nv_bfloat16 h = __float2bfloat16(v);
        __nv_bfloat16 l = __float2bfloat16(v - __bfloat162float(h));
        size_t o = (size_t)(n0 + r) * E_DIM + k0 + tx;
        dh[o] = h; dl[o] = l;
    }
}

// ---------------------------------------------------------------------------
// Projections: [4096x1024] @ W + bias -> head-split [g][s][d] bf16 hi/lo.
// BM=BN=128, KC=32, double-buffered.  smem stage: Ah Al Bh Bl (pitch 40).
// ---------------------------------------------------------------------------
#define PJ_STAGE 40960
__global__ void __launch_bounds__(256, 1)
proj_kernel(const float* __restrict__ q, const float* __restrict__ k,
            const float* __restrict__ v,
            const float* __restrict__ bq, const float* __restrict__ bk,
            const float* __restrict__ bv)
{
    extern __shared__ __align__(1024) char smem[];
    const uint32_t sb = smem_u32(smem);
    const int tid = threadIdx.x, lane = tid & 31, wid = tid >> 5;
    const int wm = wid & 1, wn = wid >> 1;
    const int mode = blockIdx.z;
    const int row0 = blockIdx.y * 128, col0 = blockIdx.x * 128;
    const float* A    = (mode == 0) ? q : (mode == 1) ? k : v;
    const float* bias = (mode == 0) ? bq : (mode == 1) ? bk : bv;
    const __nv_bfloat16* wth = g_wth + ((size_t)mode << 20);
    const __nv_bfloat16* wtl = g_wtl + ((size_t)mode << 20);

    float acc[4][4][4];
#pragma unroll
    for (int i = 0; i < 4; i++)
#pragma unroll
        for (int j = 0; j < 4; j++)
#pragma unroll
            for (int x = 0; x < 4; x++) acc[i][j][x] = 0.0f;

    float4 ar[4]; uint4 brh[2], brl[2];

#define PJ_LDG(c) do {                                                        \
    int k0 = (c) * 32;                                                        \
    _Pragma("unroll")                                                         \
    for (int t = 0; t < 4; t++) {                                             \
        int lin = tid + t * 256, r = lin >> 3, kq = (lin & 7) * 4;            \
        ar[t] = *(const float4*)(A + (size_t)(row0 + r) * E_DIM + k0 + kq);   \
    }                                                                         \
    _Pragma("unroll")                                                         \
    for (int t = 0; t < 2; t++) {                                             \
        int lin = tid + t * 256, r = lin >> 2, kq = (lin & 3) * 8;            \
        size_t o = (size_t)(col0 + r) * E_DIM + k0 + kq;                      \
        brh[t] = *(const uint4*)(wth + o);                                    \
        brl[t] = *(const uint4*)(wtl + o);                                    \
    }                                                                         \
} while (0)

#define PJ_STS(st) do {                                                       \
    char* base = smem + (st) * PJ_STAGE;                                      \
    _Pragma("unroll")                                                         \
    for (int t = 0; t < 4; t++) {                                             \
        int lin = tid + t * 256, r = lin >> 3, kq = (lin & 7) * 4;            \
        uint32_t h0, l0, h1, l1;                                              \
        split2(ar[t].x, ar[t].y, h0, l0);                                     \
        split2(ar[t].z, ar[t].w, h1, l1);                                     \
        *(uint2*)(base + (r * 40 + kq) * 2)         = make_uint2(h0, h1);     \
        *(uint2*)(base + 10240 + (r * 40 + kq) * 2) = make_uint2(l0, l1);     \
    }                                                                         \
    _Pragma("unroll")                                                         \
    for (int t = 0; t < 2; t++) {                                             \
        int lin = tid + t * 256, r = lin >> 2, kq = (lin & 3) * 8;            \
        *(uint4*)(base + 20480 + (r * 40 + kq) * 2) = brh[t];                 \
        *(uint4*)(base + 30720 + (r * 40 + kq) * 2) = brl[t];                 \
    }                                                                         \
} while (0)

    PJ_LDG(0); PJ_STS(0); __syncthreads();
    for (int c = 0; c < 32; c++) {
        int st = c & 1;
        if (c + 1 < 32) PJ_LDG(c + 1);
        uint32_t s0 = sb + st * PJ_STAGE;
        mma_block128<2, 40, 40>(acc, s0, s0 + 10240, s0 + 20480, s0 + 30720,
                                lane, wm, wn);
        if (c + 1 < 32) PJ_STS(st ^ 1);
        __syncthreads();
    }
#undef PJ_LDG
#undef PJ_STS

    __nv_bfloat16 *dh, *dl;
    if      (mode == 0) { dh = g_qh; dl = g_ql; }
    else if (mode == 1) { dh = g_kh; dl = g_kl; }
    else                { dh = g_vh; dl = g_vl; }

#pragma unroll
    for (int mt = 0; mt < 4; mt++)
#pragma unroll
        for (int nt = 0; nt < 4; nt++) {
            int c0 = col0 + wn * 32 + nt * 8 + (lane & 3) * 2;
            float b0v = __ldg(bias + c0), b1v = __ldg(bias + c0 + 1);
#pragma unroll
            for (int half = 0; half < 2; half++) {
                int r = row0 + wm * 64 + mt * 16 + (lane >> 2) + half * 8;
                float v0 = acc[mt][nt][half * 2 + 0] + b0v;
                float v1 = acc[mt][nt][half * 2 + 1] + b1v;
                uint32_t h, l; split2(v0, v1, h, l);
                int bb = r >> 11, s = r & 2047, hh = c0 >> 6, d = c0 & 63;
                size_t o = (((size_t)(bb * H_NUM + hh) * S_LEN + s) << 6) + d;
                *(uint32_t*)(dh + o) = h;
                *(uint32_t*)(dl + o) = l;
            }
        }
}

// ---------------------------------------------------------------------------
// Scores: S[g][i][j] = dot(V[i],K[j]) / 8.  BM=BN=128, K=64 single shot.
// smem: Vh Vl Kh Kl, 128x64 each, pitch 72.
// ---------------------------------------------------------------------------
__global__ void __launch_bounds__(256, 1)
scores_kernel(float* __restrict__ probs)
{
    extern __shared__ __align__(1024) char smem[];
    const uint32_t sb = smem_u32(smem);
    const int tid = threadIdx.x, lane = tid & 31, wid = tid >> 5;
    const int wm = wid & 1, wn = wid >> 1;
    const int g = blockIdx.z;
    const int i0 = blockIdx.y * 128, j0 = blockIdx.x * 128;

    const __nv_bfloat16* vh = g_vh + (((size_t)g * S_LEN + i0) << 6);
    const __nv_bfloat16* vl = g_vl + (((size_t)g * S_LEN + i0) << 6);
    const __nv_bfloat16* kh = g_kh + (((size_t)g * S_LEN + j0) << 6);
    const __nv_bfloat16* kl = g_kl + (((size_t)g * S_LEN + j0) << 6);

#pragma unroll
    for (int t = 0; t < 4; t++) {
        int lin = tid + t * 256, r = lin >> 3, dq = (lin & 7) * 8;
        size_t go = ((size_t)r << 6) + dq;
        uint32_t so = (uint32_t)((r * 72 + dq) * 2);
        *(uint4*)(smem + so)         = *(const uint4*)(vh + go);
        *(uint4*)(smem + 18432 + so) = *(const uint4*)(vl + go);
        *(uint4*)(smem + 36864 + so) = *(const uint4*)(kh + go);
        *(uint4*)(smem + 55296 + so) = *(const uint4*)(kl + go);
    }
    __syncthreads();

    float acc[4][4][4];
#pragma unroll
    for (int i = 0; i < 4; i++)
#pragma unroll
        for (int j = 0; j < 4; j++)
#pragma unroll
            for (int x = 0; x < 4; x++) acc[i][j][x] = 0.0f;

    mma_block128<4, 72, 72>(acc, sb, sb + 18432, sb + 36864, sb + 55296,
                            lane, wm, wn);

    float* Pg = probs + (size_t)g * S_LEN * S_LEN;
    const float sc = 0.125f;
#pragma unroll
    for (int mt = 0; mt < 4; mt++)
#pragma unroll
        for (int nt = 0; nt < 4; nt++) {
            int c = j0 + wn * 32 + nt * 8 + (lane & 3) * 2;
#pragma unroll
            for (int half = 0; half < 2; half++) {
                int r = i0 + wm * 64 + mt * 16 + (lane >> 2) + half * 8;
                float2 o = {acc[mt][nt][half * 2] * sc, acc[mt][nt][half * 2 + 1] * sc};
                *(float2*)(Pg + (size_t)r * S_LEN + c) = o;
            }
        }
}

// ---------------------------------------------------------------------------
// In-place row softmax over 2048 cols.
// ---------------------------------------------------------------------------
__global__ void __launch_bounds__(256)
softmax_kernel(float* __restrict__ probs)
{
    float* row = probs + (size_t)blockIdx.x * S_LEN;
    const int tid = threadIdx.x;
    __shared__ float red[8];

    float4 x0 = *(float4*)(row + tid * 4);
    float4 x1 = *(float4*)(row + tid * 4 + 1024);
    float x[8] = {x0.x, x0.y, x0.z, x0.w, x1.x, x1.y, x1.z, x1.w};

    float m = x[0];
#pragma unroll
    for (int q = 1; q < 8; q++) m = fmaxf(m, x[q]);
#pragma unroll
    for (int o = 16; o > 0; o >>= 1) m = fmaxf(m, __shfl_xor_sync(0xffffffffu, m, o));
    if ((tid & 31) == 0) red[tid >> 5] = m;
    __syncthreads();
    if (tid < 8) {
        float v = red[tid];
#pragma unroll
        for (int o = 4; o > 0; o >>= 1) v = fmaxf(v, __shfl_xor_sync(0xffu, v, o));
        if (tid == 0) red[0] = v;
    }
    __syncthreads();
    m = red[0];
    __syncthreads();

    float s = 0.0f;
#pragma unroll
    for (int q = 0; q < 8; q++) { x[q] = __expf(x[q] - m); s += x[q]; }
#pragma unroll
    for (int o = 16; o > 0; o >>= 1) s += __shfl_xor_sync(0xffffffffu, s, o);
    if ((tid & 31) == 0) red[tid >> 5] = s;
    __syncthreads();
    if (tid < 8) {
        float v = red[tid];
#pragma unroll
        for (int o = 4; o > 0; o >>= 1) v += __shfl_xor_sync(0xffu, v, o);
        if (tid == 0) red[0] = v;
    }
    __syncthreads();
    const float inv = 1.0f / red[0];

    float4 y0 = {x[0] * inv, x[1] * inv, x[2] * inv, x[3] * inv};
    float4 y1 = {x[4] * inv, x[5] * inv, x[6] * inv, x[7] * inv};
    *(float4*)(row + tid * 4)        = y0;
    *(float4*)(row + tid * 4 + 1024) = y1;
}

// ---------------------------------------------------------------------------
// attn[g][i][d] = sum_j P[i][j] * Q[j][d].  BM=128, BN=64, KC=32, NC=64.
// A = probs fp32 (split in-kernel), B = Q via ldmatrix.trans.
// smem stage (29696B): Ph(0,10240) Pl(10240) Qh(20480,4608) Ql(25088).
// ---------------------------------------------------------------------------
#define AT_STAGE 29696
__global__ void __launch_bounds__(256, 1)
attn_kernel(const float* __restrict__ probs)
{
    extern __shared__ __align__(1024) char smem[];
    const uint32_t sb = smem_u32(smem);
    const int tid = threadIdx.x, lane = tid & 31, wid = tid >> 5;
    const int wm = wid & 1, wn = wid >> 1;       // 2 M-warps x 4 N-warps (16 cols each)
    const int g = blockIdx.y;
    const int i0 = blockIdx.x * 128;
    const float* Pg = probs + (size_t)g * S_LEN * S_LEN;
    const __nv_bfloat16* qh = g_qh + (((size_t)g * S_LEN) << 6);
    const __nv_bfloat16* ql = g_ql + (((size_t)g * S_LEN) << 6);

    float acc[4][2][4];
#pragma unroll
    for (int i = 0; i < 4; i++)
#pragma unroll
        for (int j = 0; j < 2; j++)
#pragma unroll
            for (int x = 0; x < 4; x++) acc[i][j][x] = 0.0f;

    float4 pr[4]; uint4 qrh, qrl;

#define AT_LDG(c) do {                                                        \
    int k0 = (c) * 32;                                                        \
    _Pragma("unroll")                                                         \
    for (int t = 0; t < 4; t++) {                                             \
        int lin = tid + t * 256, r = lin >> 3, kq = (lin & 7) * 4;            \
        pr[t] = *(const float4*)(Pg + (size_t)(i0 + r) * S_LEN + k0 + kq);    \
    }                                                                         \
    {                                                                         \
        int r = tid >> 3, dq = (tid & 7) * 8;                                 \
        size_t o = (((size_t)(k0 + r)) << 6) + dq;                            \
        qrh = *(const uint4*)(qh + o);                                        \
        qrl = *(const uint4*)(ql + o);                                        \
    }                                                                         \
} while (0)

#define AT_STS(st) do {                                                       \
    char* base = smem + (st) * AT_STAGE;                                      \
    _Pragma("unroll")                                                         \
    for (int t = 0; t < 4; t++) {                                             \
        int lin = tid + t * 256, r = lin >> 3, kq = (lin & 7) * 4;            \
        uint32_t h0, l0, h1, l1;                                              \
        split2(pr[t].x, pr[t].y, h0, l0);                                     \
        split2(pr[t].z, pr[t].w, h1, l1);                                     \
        *(uint2*)(base + (r * 40 + kq) * 2)         = make_uint2(h0, h1);     \
        *(uint2*)(base + 10240 + (r * 40 + kq) * 2) = make_uint2(l0, l1);     \
    }                                                                         \
    {                                                                         \
        int r = tid >> 3, dq = (tid & 7) * 8;                                 \
        *(uint4*)(base + 20480 + (r * 72 + dq) * 2) = qrh;                    \
        *(uint4*)(base + 25088 + (r * 72 + dq) * 2) = qrl;                    \
    }                                                                         \
} while (0)

    AT_LDG(0); AT_STS(0); __syncthreads();
    for (int c = 0; c < 64; c++) {
        int st = c & 1;
        if (c + 1 < 64) AT_LDG(c + 1);
        uint32_t sB = sb + st * AT_STAGE;
        uint32_t sAh = sB, sAl = sB + 10240, sQh = sB + 20480, sQl = sB + 25088;
#pragma unroll
        for (int ks = 0; ks < 2; ks++) {
            uint32_t ah[4][4], al[4][4], bh[2][2], bl[2][2];
            const int arow = wm * 64 + (lane & 15);
            const int acol = ks * 16 + ((lane & 16) >> 1);
#pragma unroll
            for (int mt = 0; mt < 4; mt++) {
                uint32_t off = (uint32_t)(((arow + mt * 16) * 40 + acol) << 1);
                ldsm4(ah[mt], sAh + off);
                ldsm4(al[mt], sAl + off);
            }
            uint32_t qoff = (uint32_t)(((ks * 16 + (lane & 15)) * 72 +
                                        wn * 16 + ((lane & 16) >> 1)) << 1);
            uint32_t t4[4];
            ldsm4t(t4, sQh + qoff);
            bh[0][0] = t4[0]; bh[0][1] = t4[1]; bh[1][0] = t4[2]; bh[1][1] = t4[3];
            ldsm4t(t4, sQl + qoff);
            bl[0][0] = t4[0]; bl[0][1] = t4[1]; bl[1][0] = t4[2]; bl[1][1] = t4[3];
#pragma unroll
            for (int mt = 0; mt < 4; mt++)
#pragma unroll
                for (int nt = 0; nt < 2; nt++) {
                    mma16816(acc[mt][nt], ah[mt], bh[nt]);
                    mma16816(acc[mt][nt], ah[mt], bl[nt]);
                    mma16816(acc[mt][nt], al[mt], bh[nt]);
                }
        }
        if (c + 1 < 64) AT_STS(st ^ 1);
        __syncthreads();
    }
#undef AT_LDG
#undef AT_STS

    const int bb = g >> 4, hh = g & 15;
#pragma unroll
    for (int mt = 0; mt < 4; mt++)
#pragma unroll
        for (int nt = 0; nt < 2; nt++) {
            int d = wn * 16 + nt * 8 + (lane & 3) * 2;
#pragma unroll
            for (int half = 0; half < 2; half++) {
                int s = i0 + wm * 64 + mt * 16 + (lane >> 2) + half * 8;
                uint32_t h, l;
                split2(acc[mt][nt][half * 2], acc[mt][nt][half * 2 + 1], h, l);
                size_t o = ((size_t)(bb * S_LEN + s)) * E_DIM + hh * 64 + d;
                *(uint32_t*)(g_ah + o) = h;
                *(uint32_t*)(g_al + o) = l;
            }
        }
}

// ---------------------------------------------------------------------------
// Final: out = attn @ Wf + bf.  A already bf16 split.  BM=BN=128, KC=32.
// ---------------------------------------------------------------------------
__global__ void __launch_bounds__(256, 1)
final_kernel(const float* __restrict__ bf, float* __restrict__ out)
{
    extern __shared__ __align__(1024) char smem[];
    const uint32_t sb = smem_u32(smem);
    const int tid = threadIdx.x, lane = tid & 31, wid = tid >> 5;
    const int wm = wid & 1, wn = wid >> 1;
    const int row0 = blockIdx.y * 128, col0 = blockIdx.x * 128;
    const __nv_bfloat16* wth = g_wth + ((size_t)3 << 20);
    const __nv_bfloat16* wtl = g_wtl + ((size_t)3 << 20);

    float acc[4][4][4];
#pragma unroll
    for (int i = 0; i < 4; i++)
#pragma unroll
        for (int j = 0; j < 4; j++)
#pragma unroll
            for (int x = 0; x < 4; x++) acc[i][j][x] = 0.0f;

    uint4 arh[2], arl[2], brh[2], brl[2];

#define FN_LDG(c) do {                                                        \
    int k0 = (c) * 32;                                                        \
    _Pragma("unroll")                                                         \
    for (int t = 0; t < 2; t++) {                                             \
        int lin = tid + t * 256, r = lin >> 2, kq = (lin & 3) * 8;            \
        size_t ao = (size_t)(row0 + r) * E_DIM + k0 + kq;                     \
        arh[t] = *(const uint4*)(g_ah + ao);                                  \
        arl[t] = *(const uint4*)(g_al + ao);                                  \
        size_t bo = (size_t)(col0 + r) * E_DIM + k0 + kq;                     \
        brh[t] = *(const uint4*)(wth + bo);                                   \
        brl[t] = *(const uint4*)(wtl + bo);                                   \
    }                                                                         \
} while (0)

#define FN_STS(st) do {                                                       \
    char* base = smem + (st) * PJ_STAGE;                                      \
    _Pragma("unroll")                                                         \
    for (int t = 0; t < 2; t++) {                                             \
        int lin = tid + t * 256, r = lin >> 2, kq = (lin & 3) * 8;            \
        *(uint4*)(base + (r * 40 + kq) * 2)         = arh[t];                 \
        *(uint4*)(base + 10240 + (r * 40 + kq) * 2) = arl[t];                 \
        *(uint4*)(base + 20480 + (r * 40 + kq) * 2) = brh[t];                 \
        *(uint4*)(base + 30720 + (r * 40 + kq) * 2) = brl[t];                 \
    }                                                                         \
} while (0)

    FN_LDG(0); FN_STS(0); __syncthreads();
    for (int c = 0; c < 32; c++) {
        int st = c & 1;
        if (c + 1 < 32) FN_LDG(c + 1);
        uint32_t s0 = sb + st * PJ_STAGE;
        mma_block128<2, 40, 40>(acc, s0, s0 + 10240, s0 + 20480, s0 + 30720,
                                lane, wm, wn);
        if (c + 1 < 32) FN_STS(st ^ 1);
        __syncthreads();
    }
#undef FN_LDG
#undef FN_STS

#pragma unroll
    for (int mt = 0; mt < 4; mt++)
#pragma unroll
        for (int nt = 0; nt < 4; nt++) {
            int c0 = col0 + wn * 32 + nt * 8 + (lane & 3) * 2;
            float b0v = __ldg(bf + c0), b1v = __ldg(bf + c0 + 1);
#pragma unroll
            for (int half = 0; half < 2; half++) {
                int r = row0 + wm * 64 + mt * 16 + (lane >> 2) + half * 8;
                float2 o = {acc[mt][nt][half * 2] + b0v, acc[mt][nt][half * 2 + 1] + b1v};
                *(float2*)(out + (size_t)r * E_DIM + c0) = o;
            }
        }
}

// ---------------------------------------------------------------------------
extern "C" void kernel_launch(void* const* d_in, const int* in_sizes, int n_in,
                              void* d_out, int out_size)
{
    const float* query = (const float*)d_in[0];
    const float* key   = (const float*)d_in[1];
    const float* value = (const float*)d_in[2];
    const float* wq    = (const float*)d_in[3];
    const float* bq    = (const float*)d_in[4];
    const float* wk    = (const float*)d_in[5];
    const float* bk    = (const float*)d_in[6];
    const float* wv    = (const float*)d_in[7];
    const float* bv    = (const float*)d_in[8];
    const float* wf    = (const float*)d_in[9];
    const float* bf    = (const float*)d_in[10];

    float* out = (float*)d_out;
    const size_t probs_elems = (size_t)GH * S_LEN * S_LEN;
    size_t off = ((size_t)out_size > probs_elems) ? ((size_t)out_size - probs_elems) : 0;
    float* probs = out + off;

    const int SMEM_PJ = 2 * PJ_STAGE;   // 81920
    const int SMEM_SC = 4 * 18432;      // 73728
    const int SMEM_AT = 2 * AT_STAGE;   // 59392

    cudaFuncSetAttribute(proj_kernel,   cudaFuncAttributeMaxDynamicSharedMemorySize, SMEM_PJ);
    cudaFuncSetAttribute(scores_kernel, cudaFuncAttributeMaxDynamicSharedMemorySize, SMEM_SC);
    cudaFuncSetAttribute(attn_kernel,   cudaFuncAttributeMaxDynamicSharedMemorySize, SMEM_AT);
    cudaFuncSetAttribute(final_kernel,  cudaFuncAttributeMaxDynamicSharedMemorySize, SMEM_PJ);

    prep_w_kernel<<<dim3(32, 32, 4), dim3(32, 8)>>>(wq, wk, wv, wf);
    proj_kernel<<<dim3(8, 32, 3), 256, SMEM_PJ>>>(query, key, value, bq, bk, bv);
    scores_kernel<<<dim3(16, 16, 32), 256, SMEM_SC>>>(probs);
    softmax_kernel<<<GH * S_LEN, 256>>>(probs);
    attn_kernel<<<dim3(16, 32), 256, SMEM_AT>>>(probs);
    final_kernel<<<dim3(8, 32), 256, SMEM_PJ>>>(bf, out);
}

// round 5
// speedup vs baseline: 2.5644x; 1.0368x over previous
#include <cuda_runtime.h>
#include <cuda_bf16.h>
#include <cstdint>

#define S_LEN 2048
#define E_DIM 1024
#define H_NUM 16
#define DEPTH 64
#define BATCH 2
#define GH    (BATCH * H_NUM)
#define ROWS  (BATCH * S_LEN)

// ---------------------------------------------------------------------------
// Device scratch (allocation-free rule)
// ---------------------------------------------------------------------------
__device__ __nv_bfloat16 g_wth[4u * 1024 * 1024];          // W^T hi [mode][n][k]
__device__ __nv_bfloat16 g_wtl[4u * 1024 * 1024];          // W^T lo
__device__ __nv_bfloat16 g_qh[(size_t)GH * S_LEN * DEPTH]; // Q proj [g][s][d]
__device__ __nv_bfloat16 g_ql[(size_t)GH * S_LEN * DEPTH];
__device__ __nv_bfloat16 g_kh[(size_t)GH * S_LEN * DEPTH];
__device__ __nv_bfloat16 g_kl[(size_t)GH * S_LEN * DEPTH];
__device__ __nv_bfloat16 g_vh[(size_t)GH * S_LEN * DEPTH];
__device__ __nv_bfloat16 g_vl[(size_t)GH * S_LEN * DEPTH];
__device__ __nv_bfloat16 g_ah[(size_t)ROWS * E_DIM];       // attn out [row][col]
__device__ __nv_bfloat16 g_al[(size_t)ROWS * E_DIM];
__device__ float g_rowsum[(size_t)GH * S_LEN];             // softmax denominators

// ---------------------------------------------------------------------------
// Helpers (baseline PTX only: ldmatrix + mma.sync, sm_80-compatible)
// ---------------------------------------------------------------------------
__device__ __forceinline__ uint32_t smem_u32(const void* p) {
    uint32_t a;
    asm("{ .reg .u64 t; cvta.to.shared.u64 t, %1; cvt.u32.u64 %0, t; }"
        : "=r"(a) : "l"(p));
    return a;
}
__device__ __forceinline__ void ldsm4(uint32_t* r, uint32_t a) {
    asm volatile("ldmatrix.sync.aligned.m8n8.x4.shared.b16 {%0,%1,%2,%3}, [%4];"
                 : "=r"(r[0]), "=r"(r[1]), "=r"(r[2]), "=r"(r[3]) : "r"(a));
}
__device__ __forceinline__ void ldsm4t(uint32_t* r, uint32_t a) {
    asm volatile("ldmatrix.sync.aligned.m8n8.x4.trans.shared.b16 {%0,%1,%2,%3}, [%4];"
                 : "=r"(r[0]), "=r"(r[1]), "=r"(r[2]), "=r"(r[3]) : "r"(a));
}
__device__ __forceinline__ void mma16816(float* d, const uint32_t* a, const uint32_t* b) {
    asm volatile("mma.sync.aligned.m16n8k16.row.col.f32.bf16.bf16.f32 "
                 "{%0,%1,%2,%3}, {%4,%5,%6,%7}, {%8,%9}, {%0,%1,%2,%3};"
                 : "+f"(d[0]), "+f"(d[1]), "+f"(d[2]), "+f"(d[3])
                 : "r"(a[0]), "r"(a[1]), "r"(a[2]), "r"(a[3]), "r"(b[0]), "r"(b[1]));
}
__device__ __forceinline__ uint32_t pack_bf2(__nv_bfloat16 a, __nv_bfloat16 b) {
    return ((uint32_t)__bfloat16_as_ushort(b) << 16) | (uint32_t)__bfloat16_as_ushort(a);
}
__device__ __forceinline__ void split2(float x, float y, uint32_t& h, uint32_t& l) {
    __nv_bfloat16 hx = __float2bfloat16(x), hy = __float2bfloat16(y);
    h = pack_bf2(hx, hy);
    l = pack_bf2(__float2bfloat16(x - __bfloat162float(hx)),
                 __float2bfloat16(y - __bfloat162float(hy)));
}

// 128x128 CTA tile mma step: warp (wm,wn) computes 64x32; KSTEPS k16 steps.
// 3-term split: Ah*Bh + Ah*Bl + Al*Bh, fp32 accumulate.
template<int KSTEPS, int AP, int BP>
__device__ __forceinline__ void mma_block128(float (&acc)[4][4][4],
    uint32_t sAh, uint32_t sAl, uint32_t sBh, uint32_t sBl,
    int lane, int wm, int wn)
{
#pragma unroll
    for (int ks = 0; ks < KSTEPS; ks++) {
        uint32_t ah[4][4], al[4][4], bh[4][2], bl[4][2];
        const int arow = wm * 64 + (lane & 15);
        const int acol = ks * 16 + ((lane & 16) >> 1);
#pragma unroll
        for (int mt = 0; mt < 4; mt++) {
            uint32_t off = (uint32_t)(((arow + mt * 16) * AP + acol) << 1);
            ldsm4(ah[mt], sAh + off);
            ldsm4(al[mt], sAl + off);
        }
        const int brow = wn * 32 + (lane & 7) + ((lane & 16) >> 1);
        const int bcol = ks * 16 + (lane & 8);
#pragma unroll
        for (int p = 0; p < 2; p++) {
            uint32_t off = (uint32_t)(((brow + p * 16) * BP + bcol) << 1);
            uint32_t t4[4];
            ldsm4(t4, sBh + off);
            bh[p*2][0] = t4[0]; bh[p*2][1] = t4[1];
            bh[p*2+1][0] = t4[2]; bh[p*2+1][1] = t4[3];
            ldsm4(t4, sBl + off);
            bl[p*2][0] = t4[0]; bl[p*2][1] = t4[1];
            bl[p*2+1][0] = t4[2]; bl[p*2+1][1] = t4[3];
        }
#pragma unroll
        for (int mt = 0; mt < 4; mt++)
#pragma unroll
            for (int nt = 0; nt < 4; nt++) {
                mma16816(acc[mt][nt], ah[mt], bh[nt]);
                mma16816(acc[mt][nt], ah[mt], bl[nt]);
                mma16816(acc[mt][nt], al[mt], bh[nt]);
            }
    }
}

// ---------------------------------------------------------------------------
// Pre-pass: transpose + split the 4 weight matrices
// ---------------------------------------------------------------------------
__global__ void prep_w_kernel(const float* __restrict__ wq, const float* __restrict__ wk,
                              const float* __restrict__ wv, const float* __restrict__ wf)
{
    __shared__ float t[32][33];
    const float* W = (blockIdx.z == 0) ? wq : (blockIdx.z == 1) ? wk
                   : (blockIdx.z == 2) ? wv : wf;
    __nv_bfloat16* dh = g_wth + ((size_t)blockIdx.z << 20);
    __nv_bfloat16* dl = g_wtl + ((size_t)blockIdx.z << 20);
    int k0 = blockIdx.y * 32, n0 = blockIdx.x * 32;
    int tx = threadIdx.x, ty = threadIdx.y;
    for (int r = ty; r < 32; r += 8)
        t[r][tx] = W[(size_t)(k0 + r) * E_DIM + n0 + tx];
    __syncthreads();
    for (int r = ty; r < 32; r += 8) {
        float v = t[tx][r];
        __nv_bfloat16 h = __float2bfloat16(v);
        __nv_bfloat16 l = __float2bfloat16(v - __bfloat162float(h));
        size_t o = (size_t)(n0 + r) * E_DIM + k0 + tx;
        dh[o] = h; dl[o] = l;
    }
}

// ---------------------------------------------------------------------------
// Projections: [4096x1024] @ W + bias -> head-split [g][s][d] bf16 hi/lo.
// BM=BN=128, KC=32, double-buffered.  smem stage: Ah Al Bh Bl (pitch 40).
// ---------------------------------------------------------------------------
#define PJ_STAGE 40960
__global__ void __launch_bounds__(256, 1)
proj_kernel(const float* __restrict__ q, const float* __restrict__ k,
            const float* __restrict__ v,
            const float* __restrict__ bq, const float* __restrict__ bk,
            const float* __restrict__ bv)
{
    extern __shared__ __align__(1024) char smem[];
    const uint32_t sb = smem_u32(smem);
    const int tid = threadIdx.x, lane = tid & 31, wid = tid >> 5;
    const int wm = wid & 1, wn = wid >> 1;
    const int mode = blockIdx.z;
    const int row0 = blockIdx.y * 128, col0 = blockIdx.x * 128;
    const float* A    = (mode == 0) ? q : (mode == 1) ? k : v;
    const float* bias = (mode == 0) ? bq : (mode == 1) ? bk : bv;
    const __nv_bfloat16* wth = g_wth + ((size_t)mode << 20);
    const __nv_bfloat16* wtl = g_wtl + ((size_t)mode << 20);

    float acc[4][4][4];
#pragma unroll
    for (int i = 0; i < 4; i++)
#pragma unroll
        for (int j = 0; j < 4; j++)
#pragma unroll
            for (int x = 0; x < 4; x++) acc[i][j][x] = 0.0f;

    float4 ar[4]; uint4 brh[2], brl[2];

#define PJ_LDG(c) do {                                                        \
    int k0 = (c) * 32;                                                        \
    _Pragma("unroll")                                                         \
    for (int t = 0; t < 4; t++) {                                             \
        int lin = tid + t * 256, r = lin >> 3, kq = (lin & 7) * 4;            \
        ar[t] = *(const float4*)(A + (size_t)(row0 + r) * E_DIM + k0 + kq);   \
    }                                                                         \
    _Pragma("unroll")                                                         \
    for (int t = 0; t < 2; t++) {                                             \
        int lin = tid + t * 256, r = lin >> 2, kq = (lin & 3) * 8;            \
        size_t o = (size_t)(col0 + r) * E_DIM + k0 + kq;                      \
        brh[t] = *(const uint4*)(wth + o);                                    \
        brl[t] = *(const uint4*)(wtl + o);                                    \
    }                                                                         \
} while (0)

#define PJ_STS(st) do {                                                       \
    char* base = smem + (st) * PJ_STAGE;                                      \
    _Pragma("unroll")                                                         \
    for (int t = 0; t < 4; t++) {                                             \
        int lin = tid + t * 256, r = lin >> 3, kq = (lin & 7) * 4;            \
        uint32_t h0, l0, h1, l1;                                              \
        split2(ar[t].x, ar[t].y, h0, l0);                                     \
        split2(ar[t].z, ar[t].w, h1, l1);                                     \
        *(uint2*)(base + (r * 40 + kq) * 2)         = make_uint2(h0, h1);     \
        *(uint2*)(base + 10240 + (r * 40 + kq) * 2) = make_uint2(l0, l1);     \
    }                                                                         \
    _Pragma("unroll")                                                         \
    for (int t = 0; t < 2; t++) {                                             \
        int lin = tid + t * 256, r = lin >> 2, kq = (lin & 3) * 8;            \
        *(uint4*)(base + 20480 + (r * 40 + kq) * 2) = brh[t];                 \
        *(uint4*)(base + 30720 + (r * 40 + kq) * 2) = brl[t];                 \
    }                                                                         \
} while (0)

    PJ_LDG(0); PJ_STS(0); __syncthreads();
    for (int c = 0; c < 32; c++) {
        int st = c & 1;
        if (c + 1 < 32) PJ_LDG(c + 1);
        uint32_t s0 = sb + st * PJ_STAGE;
        mma_block128<2, 40, 40>(acc, s0, s0 + 10240, s0 + 20480, s0 + 30720,
                                lane, wm, wn);
        if (c + 1 < 32) PJ_STS(st ^ 1);
        __syncthreads();
    }
#undef PJ_LDG
#undef PJ_STS

    __nv_bfloat16 *dh, *dl;
    if      (mode == 0) { dh = g_qh; dl = g_ql; }
    else if (mode == 1) { dh = g_kh; dl = g_kl; }
    else                { dh = g_vh; dl = g_vl; }

#pragma unroll
    for (int mt = 0; mt < 4; mt++)
#pragma unroll
        for (int nt = 0; nt < 4; nt++) {
            int c0 = col0 + wn * 32 + nt * 8 + (lane & 3) * 2;
            float b0v = __ldg(bias + c0), b1v = __ldg(bias + c0 + 1);
#pragma unroll
            for (int half = 0; half < 2; half++) {
                int r = row0 + wm * 64 + mt * 16 + (lane >> 2) + half * 8;
                float v0 = acc[mt][nt][half * 2 + 0] + b0v;
                float v1 = acc[mt][nt][half * 2 + 1] + b1v;
                uint32_t h, l; split2(v0, v1, h, l);
                int bb = r >> 11, s = r & 2047, hh = c0 >> 6, d = c0 & 63;
                size_t o = (((size_t)(bb * H_NUM + hh) * S_LEN + s) << 6) + d;
                *(uint32_t*)(dh + o) = h;
                *(uint32_t*)(dl + o) = l;
            }
        }
}

// ---------------------------------------------------------------------------
// Scores (fused exp + row sums): one CTA per (g, 128-row strip).
// V loaded once; K streamed over 16 j-tiles (double-buffered).
// Writes probs = exp(V.K/8) (unnormalized) and g_rowsum = per-row sums.
// smem: Vh(0) Vl(18432) | Kbuf0 {h,l}(36864) Kbuf1(73728) | srow(110592)
// ---------------------------------------------------------------------------
#define SC_KBUF 36864
__global__ void __launch_bounds__(256, 1)
scores_kernel(float* __restrict__ probs)
{
    extern __shared__ __align__(1024) char smem[];
    const uint32_t sb = smem_u32(smem);
    const int tid = threadIdx.x, lane = tid & 31, wid = tid >> 5;
    const int wm = wid & 1, wn = wid >> 1;
    const int g = blockIdx.y;
    const int i0 = blockIdx.x * 128;
    float* srow = (float*)(smem + 110592);

    const __nv_bfloat16* vh = g_vh + (((size_t)g * S_LEN + i0) << 6);
    const __nv_bfloat16* vl = g_vl + (((size_t)g * S_LEN + i0) << 6);
    const __nv_bfloat16* kh = g_kh + (((size_t)g * S_LEN) << 6);
    const __nv_bfloat16* kl = g_kl + (((size_t)g * S_LEN) << 6);
    float* Pg = probs + (size_t)g * S_LEN * S_LEN;

    // V tiles (128x64 hi/lo, pitch 72)
#pragma unroll
    for (int t = 0; t < 4; t++) {
        int lin = tid + t * 256, r = lin >> 3, dq = (lin & 7) * 8;
        size_t go = ((size_t)r << 6) + dq;
        uint32_t so = (uint32_t)((r * 72 + dq) * 2);
        *(uint4*)(smem + so)         = *(const uint4*)(vh + go);
        *(uint4*)(smem + 18432 + so) = *(const uint4*)(vl + go);
    }
    if (tid < 128) srow[tid] = 0.0f;

    uint4 krh[4], krl[4];
#define SC_KLDG(j) do {                                                       \
    int j0 = (j) * 128;                                                       \
    _Pragma("unroll")                                                         \
    for (int t = 0; t < 4; t++) {                                             \
        int lin = tid + t * 256, r = lin >> 3, dq = (lin & 7) * 8;            \
        size_t go = (((size_t)(j0 + r)) << 6) + dq;                           \
        krh[t] = *(const uint4*)(kh + go);                                    \
        krl[t] = *(const uint4*)(kl + go);                                    \
    }                                                                         \
} while (0)
#define SC_KSTS(st) do {                                                      \
    char* base = smem + 36864 + (st) * SC_KBUF;                               \
    _Pragma("unroll")                                                         \
    for (int t = 0; t < 4; t++) {                                             \
        int lin = tid + t * 256, r = lin >> 3, dq = (lin & 7) * 8;            \
        uint32_t so = (uint32_t)((r * 72 + dq) * 2);                          \
        *(uint4*)(base + so)         = krh[t];                                \
        *(uint4*)(base + 18432 + so) = krl[t];                                \
    }                                                                         \
} while (0)

    float rsum[4][2];
#pragma unroll
    for (int i = 0; i < 4; i++) { rsum[i][0] = 0.0f; rsum[i][1] = 0.0f; }

    SC_KLDG(0); SC_KSTS(0); __syncthreads();
    for (int j = 0; j < 16; j++) {
        const int st = j & 1;
        if (j + 1 < 16) SC_KLDG(j + 1);

        float acc[4][4][4];
#pragma unroll
        for (int i = 0; i < 4; i++)
#pragma unroll
            for (int jj = 0; jj < 4; jj++)
#pragma unroll
                for (int x = 0; x < 4; x++) acc[i][jj][x] = 0.0f;

        uint32_t kb = sb + 36864 + st * SC_KBUF;
        mma_block128<4, 72, 72>(acc, sb, sb + 18432, kb, kb + 18432,
                                lane, wm, wn);

        const int j0 = j * 128;
#pragma unroll
        for (int mt = 0; mt < 4; mt++)
#pragma unroll
            for (int nt = 0; nt < 4; nt++) {
                int c = j0 + wn * 32 + nt * 8 + (lane & 3) * 2;
#pragma unroll
                for (int half = 0; half < 2; half++) {
                    int r = i0 + wm * 64 + mt * 16 + (lane >> 2) + half * 8;
                    float p0 = __expf(fminf(acc[mt][nt][half * 2 + 0] * 0.125f, 80.0f));
                    float p1 = __expf(fminf(acc[mt][nt][half * 2 + 1] * 0.125f, 80.0f));
                    rsum[mt][half] += p0 + p1;
                    *(float2*)(Pg + (size_t)r * S_LEN + c) = make_float2(p0, p1);
                }
            }

        if (j + 1 < 16) SC_KSTS(st ^ 1);
        __syncthreads();
    }
#undef SC_KLDG
#undef SC_KSTS

    // Reduce row sums: quad shuffle (cols) then smem atomic across wn warps.
#pragma unroll
    for (int mt = 0; mt < 4; mt++)
#pragma unroll
        for (int half = 0; half < 2; half++) {
            float v = rsum[mt][half];
            v += __shfl_xor_sync(0xffffffffu, v, 1);
            v += __shfl_xor_sync(0xffffffffu, v, 2);
            if ((lane & 3) == 0)
                atomicAdd(&srow[wm * 64 + mt * 16 + (lane >> 2) + half * 8], v);
        }
    __syncthreads();
    if (tid < 128) g_rowsum[(size_t)g * S_LEN + i0 + tid] = srow[tid];
}

// ---------------------------------------------------------------------------
// attn[g][i][d] = sum_j softmax(P)[i][j] * Q[j][d].  Also writes the
// normalized probs back to gmem (softmax output).  BM=128, BN=64, KC=32.
// smem stage (29696B): Ph(0) Pl(10240) Qh(20480) Ql(25088); invZ at 59392.
// ---------------------------------------------------------------------------
#define AT_STAGE 29696
__global__ void __launch_bounds__(256, 1)
attn_kernel(float* __restrict__ probs)
{
    extern __shared__ __align__(1024) char smem[];
    const uint32_t sb = smem_u32(smem);
    const int tid = threadIdx.x, lane = tid & 31, wid = tid >> 5;
    const int wm = wid & 1, wn = wid >> 1;
    const int g = blockIdx.y;
    const int i0 = blockIdx.x * 128;
    float* Pg = probs + (size_t)g * S_LEN * S_LEN;
    const __nv_bfloat16* qh = g_qh + (((size_t)g * S_LEN) << 6);
    const __nv_bfloat16* ql = g_ql + (((size_t)g * S_LEN) << 6);
    float* inv = (float*)(smem + 2 * AT_STAGE);

    if (tid < 128)
        inv[tid] = 1.0f / g_rowsum[(size_t)g * S_LEN + i0 + tid];
    __syncthreads();

    float acc[4][2][4];
#pragma unroll
    for (int i = 0; i < 4; i++)
#pragma unroll
        for (int j = 0; j < 2; j++)
#pragma unroll
            for (int x = 0; x < 4; x++) acc[i][j][x] = 0.0f;

    float4 pr[4]; uint4 qrh, qrl;

#define AT_LDG(c) do {                                                        \
    int k0 = (c) * 32;                                                        \
    _Pragma("unroll")                                                         \
    for (int t = 0; t < 4; t++) {                                             \
        int lin = tid + t * 256, r = lin >> 3, kq = (lin & 7) * 4;            \
        pr[t] = *(const float4*)(Pg + (size_t)(i0 + r) * S_LEN + k0 + kq);    \
    }                                                                         \
    {                                                                         \
        int r = tid >> 3, dq = (tid & 7) * 8;                                 \
        size_t o = (((size_t)(k0 + r)) << 6) + dq;                            \
        qrh = *(const uint4*)(qh + o);                                        \
        qrl = *(const uint4*)(ql + o);                                        \
    }                                                                         \
} while (0)

// Normalize, store normalized probs to gmem, split to smem for MMA.
#define AT_STS(st, c) do {                                                    \
    char* base = smem + (st) * AT_STAGE;                                      \
    int k0 = (c) * 32;                                                        \
    _Pragma("unroll")                                                         \
    for (int t = 0; t < 4; t++) {                                             \
        int lin = tid + t * 256, r = lin >> 3, kq = (lin & 7) * 4;            \
        float iz = inv[r];                                                    \
        float4 pn;                                                            \
        pn.x = pr[t].x * iz; pn.y = pr[t].y * iz;                             \
        pn.z = pr[t].z * iz; pn.w = pr[t].w * iz;                             \
        *(float4*)(Pg + (size_t)(i0 + r) * S_LEN + k0 + kq) = pn;             \
        uint32_t h0, l0, h1, l1;                                              \
        split2(pn.x, pn.y, h0, l0);                                           \
        split2(pn.z, pn.w, h1, l1);                                           \
        *(uint2*)(base + (r * 40 + kq) * 2)         = make_uint2(h0, h1);     \
        *(uint2*)(base + 10240 + (r * 40 + kq) * 2) = make_uint2(l0, l1);     \
    }                                                                         \
    {                                                                         \
        int r = tid >> 3, dq = (tid & 7) * 8;                                 \
        *(uint4*)(base + 20480 + (r * 72 + dq) * 2) = qrh;                    \
        *(uint4*)(base + 25088 + (r * 72 + dq) * 2) = qrl;                    \
    }                                                                         \
} while (0)

    AT_LDG(0); AT_STS(0, 0); __syncthreads();
    for (int c = 0; c < 64; c++) {
        int st = c & 1;
        if (c + 1 < 64) AT_LDG(c + 1);
        uint32_t sB = sb + st * AT_STAGE;
        uint32_t sAh = sB, sAl = sB + 10240, sQh = sB + 20480, sQl = sB + 25088;
#pragma unroll
        for (int ks = 0; ks < 2; ks++) {
            uint32_t ah[4][4], al[4][4], bh[2][2], bl[2][2];
            const int arow = wm * 64 + (lane & 15);
            const int acol = ks * 16 + ((lane & 16) >> 1);
#pragma unroll
            for (int mt = 0; mt < 4; mt++) {
                uint32_t off = (uint32_t)(((arow + mt * 16) * 40 + acol) << 1);
                ldsm4(ah[mt], sAh + off);
                ldsm4(al[mt], sAl + off);
            }
            uint32_t qoff = (uint32_t)(((ks * 16 + (lane & 15)) * 72 +
                                        wn * 16 + ((lane & 16) >> 1)) << 1);
            uint32_t t4[4];
            ldsm4t(t4, sQh + qoff);
            bh[0][0] = t4[0]; bh[0][1] = t4[1]; bh[1][0] = t4[2]; bh[1][1] = t4[3];
            ldsm4t(t4, sQl + qoff);
            bl[0][0] = t4[0]; bl[0][1] = t4[1]; bl[1][0] = t4[2]; bl[1][1] = t4[3];
#pragma unroll
            for (int mt = 0; mt < 4; mt++)
#pragma unroll
                for (int nt = 0; nt < 2; nt++) {
                    mma16816(acc[mt][nt], ah[mt], bh[nt]);
                    mma16816(acc[mt][nt], ah[mt], bl[nt]);
                    mma16816(acc[mt][nt], al[mt], bh[nt]);
                }
        }
        if (c + 1 < 64) AT_STS(st ^ 1, c + 1);
        __syncthreads();
    }
#undef AT_LDG
#undef AT_STS

    const int bb = g >> 4, hh = g & 15;
#pragma unroll
    for (int mt = 0; mt < 4; mt++)
#pragma unroll
        for (int nt = 0; nt < 2; nt++) {
            int d = wn * 16 + nt * 8 + (lane & 3) * 2;
#pragma unroll
            for (int half = 0; half < 2; half++) {
                int s = i0 + wm * 64 + mt * 16 + (lane >> 2) + half * 8;
                uint32_t h, l;
                split2(acc[mt][nt][half * 2], acc[mt][nt][half * 2 + 1], h, l);
                size_t o = ((size_t)(bb * S_LEN + s)) * E_DIM + hh * 64 + d;
                *(uint32_t*)(g_ah + o) = h;
                *(uint32_t*)(g_al + o) = l;
            }
        }
}

// ---------------------------------------------------------------------------
// Final: out = attn @ Wf + bf.  A already bf16 split.  BM=BN=128, KC=32.
// ---------------------------------------------------------------------------
__global__ void __launch_bounds__(256, 1)
final_kernel(const float* __restrict__ bf, float* __restrict__ out)
{
    extern __shared__ __align__(1024) char smem[];
    const uint32_t sb = smem_u32(smem);
    const int tid = threadIdx.x, lane = tid & 31, wid = tid >> 5;
    const int wm = wid & 1, wn = wid >> 1;
    const int row0 = blockIdx.y * 128, col0 = blockIdx.x * 128;
    const __nv_bfloat16* wth = g_wth + ((size_t)3 << 20);
    const __nv_bfloat16* wtl = g_wtl + ((size_t)3 << 20);

    float acc[4][4][4];
#pragma unroll
    for (int i = 0; i < 4; i++)
#pragma unroll
        for (int j = 0; j < 4; j++)
#pragma unroll
            for (int x = 0; x < 4; x++) acc[i][j][x] = 0.0f;

    uint4 arh[2], arl[2], brh[2], brl[2];

#define FN_LDG(c) do {                                                        \
    int k0 = (c) * 32;                                                        \
    _Pragma("unroll")                                                         \
    for (int t = 0; t < 2; t++) {                                             \
        int lin = tid + t * 256, r = lin >> 2, kq = (lin & 3) * 8;            \
        size_t ao = (size_t)(row0 + r) * E_DIM + k0 + kq;                     \
        arh[t] = *(const uint4*)(g_ah + ao);                                  \
        arl[t] = *(const uint4*)(g_al + ao);                                  \
        size_t bo = (size_t)(col0 + r) * E_DIM + k0 + kq;                     \
        brh[t] = *(const uint4*)(wth + bo);                                   \
        brl[t] = *(const uint4*)(wtl + bo);                                   \
    }                                                                         \
} while (0)

#define FN_STS(st) do {                                                       \
    char* base = smem + (st) * PJ_STAGE;                                      \
    _Pragma("unroll")                                                         \
    for (int t = 0; t < 2; t++) {                                             \
        int lin = tid + t * 256, r = lin >> 2, kq = (lin & 3) * 8;            \
        *(uint4*)(base + (r * 40 + kq) * 2)         = arh[t];                 \
        *(uint4*)(base + 10240 + (r * 40 + kq) * 2) = arl[t];                 \
        *(uint4*)(base + 20480 + (r * 40 + kq) * 2) = brh[t];                 \
        *(uint4*)(base + 30720 + (r * 40 + kq) * 2) = brl[t];                 \
    }                                                                         \
} while (0)

    FN_LDG(0); FN_STS(0); __syncthreads();
    for (int c = 0; c < 32; c++) {
        int st = c & 1;
        if (c + 1 < 32) FN_LDG(c + 1);
        uint32_t s0 = sb + st * PJ_STAGE;
        mma_block128<2, 40, 40>(acc, s0, s0 + 10240, s0 + 20480, s0 + 30720,
                                lane, wm, wn);
        if (c + 1 < 32) FN_STS(st ^ 1);
        __syncthreads();
    }
#undef FN_LDG
#undef FN_STS

#pragma unroll
    for (int mt = 0; mt < 4; mt++)
#pragma unroll
        for (int nt = 0; nt < 4; nt++) {
            int c0 = col0 + wn * 32 + nt * 8 + (lane & 3) * 2;
            float b0v = __ldg(bf + c0), b1v = __ldg(bf + c0 + 1);
#pragma unroll
            for (int half = 0; half < 2; half++) {
                int r = row0 + wm * 64 + mt * 16 + (lane >> 2) + half * 8;
                float2 o = {acc[mt][nt][half * 2] + b0v, acc[mt][nt][half * 2 + 1] + b1v};
                *(float2*)(out + (size_t)r * E_DIM + c0) = o;
            }
        }
}

// ---------------------------------------------------------------------------
extern "C" void kernel_launch(void* const* d_in, const int* in_sizes, int n_in,
                              void* d_out, int out_size)
{
    const float* query = (const float*)d_in[0];
    const float* key   = (const float*)d_in[1];
    const float* value = (const float*)d_in[2];
    const float* wq    = (const float*)d_in[3];
    const float* bq    = (const float*)d_in[4];
    const float* wk    = (const float*)d_in[5];
    const float* bk    = (const float*)d_in[6];
    const float* wv    = (const float*)d_in[7];
    const float* bv    = (const float*)d_in[8];
    const float* wf    = (const float*)d_in[9];
    const float* bf    = (const float*)d_in[10];

    float* out = (float*)d_out;
    const size_t probs_elems = (size_t)GH * S_LEN * S_LEN;
    size_t off = ((size_t)out_size > probs_elems) ? ((size_t)out_size - probs_elems) : 0;
    float* probs = out + off;

    const int SMEM_PJ = 2 * PJ_STAGE;          // 81920
    const int SMEM_SC = 110592 + 512;          // V + 2 Kbuf + srow
    const int SMEM_AT = 2 * AT_STAGE + 512;    // 59904

    cudaFuncSetAttribute(proj_kernel,   cudaFuncAttributeMaxDynamicSharedMemorySize, SMEM_PJ);
    cudaFuncSetAttribute(scores_kernel, cudaFuncAttributeMaxDynamicSharedMemorySize, SMEM_SC);
    cudaFuncSetAttribute(attn_kernel,   cudaFuncAttributeMaxDynamicSharedMemorySize, SMEM_AT);
    cudaFuncSetAttribute(final_kernel,  cudaFuncAttributeMaxDynamicSharedMemorySize, SMEM_PJ);

    prep_w_kernel<<<dim3(32, 32, 4), dim3(32, 8)>>>(wq, wk, wv, wf);
    proj_kernel<<<dim3(8, 32, 3), 256, SMEM_PJ>>>(query, key, value, bq, bk, bv);
    scores_kernel<<<dim3(16, 32), 256, SMEM_SC>>>(probs);
    attn_kernel<<<dim3(16, 32), 256, SMEM_AT>>>(probs);
    final_kernel<<<dim3(8, 32), 256, SMEM_PJ>>>(bf, out);
}

// round 6
// speedup vs baseline: 2.9981x; 1.1692x over previous
#include <cuda_runtime.h>
#include <cuda_bf16.h>
#include <cstdint>

#define S_LEN 2048
#define E_DIM 1024
#define H_NUM 16
#define DEPTH 64
#define BATCH 2
#define GH    (BATCH * H_NUM)
#define ROWS  (BATCH * S_LEN)

// ---------------------------------------------------------------------------
// Device scratch (allocation-free rule)
// ---------------------------------------------------------------------------
__device__ __nv_bfloat16 g_wth[4u * 1024 * 1024];          // W^T hi [mode][n][k]
__device__ __nv_bfloat16 g_wtl[4u * 1024 * 1024];          // W^T lo
__device__ __nv_bfloat16 g_qh[(size_t)GH * S_LEN * DEPTH]; // Q proj [g][s][d]
__device__ __nv_bfloat16 g_ql[(size_t)GH * S_LEN * DEPTH];
__device__ __nv_bfloat16 g_kh[(size_t)GH * S_LEN * DEPTH];
__device__ __nv_bfloat16 g_kl[(size_t)GH * S_LEN * DEPTH];
__device__ __nv_bfloat16 g_vh[(size_t)GH * S_LEN * DEPTH];
__device__ __nv_bfloat16 g_vl[(size_t)GH * S_LEN * DEPTH];
__device__ __nv_bfloat16 g_ah[(size_t)ROWS * E_DIM];       // attn out [row][col]
__device__ __nv_bfloat16 g_al[(size_t)ROWS * E_DIM];
__device__ float g_rowsum[(size_t)GH * S_LEN];             // softmax denominators

// ---------------------------------------------------------------------------
// Helpers (baseline PTX only: ldmatrix + mma.sync + cp.async, sm_80-level)
// ---------------------------------------------------------------------------
__device__ __forceinline__ uint32_t smem_u32(const void* p) {
    uint32_t a;
    asm("{ .reg .u64 t; cvta.to.shared.u64 t, %1; cvt.u32.u64 %0, t; }"
        : "=r"(a) : "l"(p));
    return a;
}
__device__ __forceinline__ void ldsm4(uint32_t* r, uint32_t a) {
    asm volatile("ldmatrix.sync.aligned.m8n8.x4.shared.b16 {%0,%1,%2,%3}, [%4];"
                 : "=r"(r[0]), "=r"(r[1]), "=r"(r[2]), "=r"(r[3]) : "r"(a));
}
__device__ __forceinline__ void ldsm4t(uint32_t* r, uint32_t a) {
    asm volatile("ldmatrix.sync.aligned.m8n8.x4.trans.shared.b16 {%0,%1,%2,%3}, [%4];"
                 : "=r"(r[0]), "=r"(r[1]), "=r"(r[2]), "=r"(r[3]) : "r"(a));
}
__device__ __forceinline__ void mma16816(float* d, const uint32_t* a, const uint32_t* b) {
    asm volatile("mma.sync.aligned.m16n8k16.row.col.f32.bf16.bf16.f32 "
                 "{%0,%1,%2,%3}, {%4,%5,%6,%7}, {%8,%9}, {%0,%1,%2,%3};"
                 : "+f"(d[0]), "+f"(d[1]), "+f"(d[2]), "+f"(d[3])
                 : "r"(a[0]), "r"(a[1]), "r"(a[2]), "r"(a[3]), "r"(b[0]), "r"(b[1]));
}
__device__ __forceinline__ void cp16(uint32_t dst, const void* src) {
    asm volatile("cp.async.cg.shared.global [%0], [%1], 16;"
                 :: "r"(dst), "l"(src));
}
#define CP_COMMIT() asm volatile("cp.async.commit_group;" ::: "memory")
#define CP_WAIT1()  asm volatile("cp.async.wait_group 1;" ::: "memory")

__device__ __forceinline__ uint32_t pack_bf2(__nv_bfloat16 a, __nv_bfloat16 b) {
    return ((uint32_t)__bfloat16_as_ushort(b) << 16) | (uint32_t)__bfloat16_as_ushort(a);
}
__device__ __forceinline__ void split2(float x, float y, uint32_t& h, uint32_t& l) {
    __nv_bfloat16 hx = __float2bfloat16(x), hy = __float2bfloat16(y);
    h = pack_bf2(hx, hy);
    l = pack_bf2(__float2bfloat16(x - __bfloat162float(hx)),
                 __float2bfloat16(y - __bfloat162float(hy)));
}

// 128x128 CTA tile mma step: warp (wm,wn) computes 64x32; KSTEPS k16 steps.
template<int KSTEPS, int AP, int BP>
__device__ __forceinline__ void mma_block128(float (&acc)[4][4][4],
    uint32_t sAh, uint32_t sAl, uint32_t sBh, uint32_t sBl,
    int lane, int wm, int wn)
{
#pragma unroll
    for (int ks = 0; ks < KSTEPS; ks++) {
        uint32_t ah[4][4], al[4][4], bh[4][2], bl[4][2];
        const int arow = wm * 64 + (lane & 15);
        const int acol = ks * 16 + ((lane & 16) >> 1);
#pragma unroll
        for (int mt = 0; mt < 4; mt++) {
            uint32_t off = (uint32_t)(((arow + mt * 16) * AP + acol) << 1);
            ldsm4(ah[mt], sAh + off);
            ldsm4(al[mt], sAl + off);
        }
        const int brow = wn * 32 + (lane & 7) + ((lane & 16) >> 1);
        const int bcol = ks * 16 + (lane & 8);
#pragma unroll
        for (int p = 0; p < 2; p++) {
            uint32_t off = (uint32_t)(((brow + p * 16) * BP + bcol) << 1);
            uint32_t t4[4];
            ldsm4(t4, sBh + off);
            bh[p*2][0] = t4[0]; bh[p*2][1] = t4[1];
            bh[p*2+1][0] = t4[2]; bh[p*2+1][1] = t4[3];
            ldsm4(t4, sBl + off);
            bl[p*2][0] = t4[0]; bl[p*2][1] = t4[1];
            bl[p*2+1][0] = t4[2]; bl[p*2+1][1] = t4[3];
        }
#pragma unroll
        for (int mt = 0; mt < 4; mt++)
#pragma unroll
            for (int nt = 0; nt < 4; nt++) {
                mma16816(acc[mt][nt], ah[mt], bh[nt]);
                mma16816(acc[mt][nt], ah[mt], bl[nt]);
                mma16816(acc[mt][nt], al[mt], bh[nt]);
            }
    }
}

// N=64 variant: warp (wm,wn) computes 64x16 (nt=2).
template<int KSTEPS, int AP, int BP>
__device__ __forceinline__ void mma_n64(float (&acc)[4][2][4],
    uint32_t sAh, uint32_t sAl, uint32_t sBh, uint32_t sBl,
    int lane, int wm, int wn)
{
#pragma unroll
    for (int ks = 0; ks < KSTEPS; ks++) {
        uint32_t ah[4][4], al[4][4], bh[2][2], bl[2][2];
        const int arow = wm * 64 + (lane & 15);
        const int acol = ks * 16 + ((lane & 16) >> 1);
#pragma unroll
        for (int mt = 0; mt < 4; mt++) {
            uint32_t off = (uint32_t)(((arow + mt * 16) * AP + acol) << 1);
            ldsm4(ah[mt], sAh + off);
            ldsm4(al[mt], sAl + off);
        }
        const int brow = wn * 16 + (lane & 7) + ((lane & 16) >> 1);
        const int bcol = ks * 16 + (lane & 8);
        {
            uint32_t off = (uint32_t)((brow * BP + bcol) << 1);
            uint32_t t4[4];
            ldsm4(t4, sBh + off);
            bh[0][0] = t4[0]; bh[0][1] = t4[1]; bh[1][0] = t4[2]; bh[1][1] = t4[3];
            ldsm4(t4, sBl + off);
            bl[0][0] = t4[0]; bl[0][1] = t4[1]; bl[1][0] = t4[2]; bl[1][1] = t4[3];
        }
#pragma unroll
        for (int mt = 0; mt < 4; mt++)
#pragma unroll
            for (int nt = 0; nt < 2; nt++) {
                mma16816(acc[mt][nt], ah[mt], bh[nt]);
                mma16816(acc[mt][nt], ah[mt], bl[nt]);
                mma16816(acc[mt][nt], al[mt], bh[nt]);
            }
    }
}

// ---------------------------------------------------------------------------
// Pre-pass: transpose + split the 4 weight matrices
// ---------------------------------------------------------------------------
__global__ void prep_w_kernel(const float* __restrict__ wq, const float* __restrict__ wk,
                              const float* __restrict__ wv, const float* __restrict__ wf)
{
    __shared__ float t[32][33];
    const float* W = (blockIdx.z == 0) ? wq : (blockIdx.z == 1) ? wk
                   : (blockIdx.z == 2) ? wv : wf;
    __nv_bfloat16* dh = g_wth + ((size_t)blockIdx.z << 20);
    __nv_bfloat16* dl = g_wtl + ((size_t)blockIdx.z << 20);
    int k0 = blockIdx.y * 32, n0 = blockIdx.x * 32;
    int tx = threadIdx.x, ty = threadIdx.y;
    for (int r = ty; r < 32; r += 8)
        t[r][tx] = W[(size_t)(k0 + r) * E_DIM + n0 + tx];
    __syncthreads();
    for (int r = ty; r < 32; r += 8) {
        float v = t[tx][r];
        __nv_bfloat16 h = __float2bfloat16(v);
        __nv_bfloat16 l = __float2bfloat16(v - __bfloat162float(h));
        size_t o = (size_t)(n0 + r) * E_DIM + k0 + tx;
        dh[o] = h; dl[o] = l;
    }
}

// ---------------------------------------------------------------------------
// Projections: [4096x1024] @ W + bias -> head-split [g][s][d] bf16 hi/lo.
// BM=BN=128, KC=32, double-buffered.  smem stage: Ah Al Bh Bl (pitch 40).
// ---------------------------------------------------------------------------
#define PJ_STAGE 40960
__global__ void __launch_bounds__(256, 1)
proj_kernel(const float* __restrict__ q, const float* __restrict__ k,
            const float* __restrict__ v,
            const float* __restrict__ bq, const float* __restrict__ bk,
            const float* __restrict__ bv)
{
    extern __shared__ __align__(1024) char smem[];
    const uint32_t sb = smem_u32(smem);
    const int tid = threadIdx.x, lane = tid & 31, wid = tid >> 5;
    const int wm = wid & 1, wn = wid >> 1;
    const int mode = blockIdx.z;
    const int row0 = blockIdx.y * 128, col0 = blockIdx.x * 128;
    const float* A    = (mode == 0) ? q : (mode == 1) ? k : v;
    const float* bias = (mode == 0) ? bq : (mode == 1) ? bk : bv;
    const __nv_bfloat16* wth = g_wth + ((size_t)mode << 20);
    const __nv_bfloat16* wtl = g_wtl + ((size_t)mode << 20);

    float acc[4][4][4];
#pragma unroll
    for (int i = 0; i < 4; i++)
#pragma unroll
        for (int j = 0; j < 4; j++)
#pragma unroll
            for (int x = 0; x < 4; x++) acc[i][j][x] = 0.0f;

    float4 ar[4]; uint4 brh[2], brl[2];

#define PJ_LDG(c) do {                                                        \
    int k0 = (c) * 32;                                                        \
    _Pragma("unroll")                                                         \
    for (int t = 0; t < 4; t++) {                                             \
        int lin = tid + t * 256, r = lin >> 3, kq = (lin & 7) * 4;            \
        ar[t] = *(const float4*)(A + (size_t)(row0 + r) * E_DIM + k0 + kq);   \
    }                                                                         \
    _Pragma("unroll")                                                         \
    for (int t = 0; t < 2; t++) {                                             \
        int lin = tid + t * 256, r = lin >> 2, kq = (lin & 3) * 8;            \
        size_t o = (size_t)(col0 + r) * E_DIM + k0 + kq;                      \
        brh[t] = *(const uint4*)(wth + o);                                    \
        brl[t] = *(const uint4*)(wtl + o);                                    \
    }                                                                         \
} while (0)

#define PJ_STS(st) do {                                                       \
    char* base = smem + (st) * PJ_STAGE;                                      \
    _Pragma("unroll")                                                         \
    for (int t = 0; t < 4; t++) {                                             \
        int lin = tid + t * 256, r = lin >> 3, kq = (lin & 7) * 4;            \
        uint32_t h0, l0, h1, l1;                                              \
        split2(ar[t].x, ar[t].y, h0, l0);                                     \
        split2(ar[t].z, ar[t].w, h1, l1);                                     \
        *(uint2*)(base + (r * 40 + kq) * 2)         = make_uint2(h0, h1);     \
        *(uint2*)(base + 10240 + (r * 40 + kq) * 2) = make_uint2(l0, l1);     \
    }                                                                         \
    _Pragma("unroll")                                                         \
    for (int t = 0; t < 2; t++) {                                             \
        int lin = tid + t * 256, r = lin >> 2, kq = (lin & 3) * 8;            \
        *(uint4*)(base + 20480 + (r * 40 + kq) * 2) = brh[t];                 \
        *(uint4*)(base + 30720 + (r * 40 + kq) * 2) = brl[t];                 \
    }                                                                         \
} while (0)

    PJ_LDG(0); PJ_STS(0); __syncthreads();
    for (int c = 0; c < 32; c++) {
        int st = c & 1;
        if (c + 1 < 32) PJ_LDG(c + 1);
        uint32_t s0 = sb + st * PJ_STAGE;
        mma_block128<2, 40, 40>(acc, s0, s0 + 10240, s0 + 20480, s0 + 30720,
                                lane, wm, wn);
        if (c + 1 < 32) PJ_STS(st ^ 1);
        __syncthreads();
    }
#undef PJ_LDG
#undef PJ_STS

    __nv_bfloat16 *dh, *dl;
    if      (mode == 0) { dh = g_qh; dl = g_ql; }
    else if (mode == 1) { dh = g_kh; dl = g_kl; }
    else                { dh = g_vh; dl = g_vl; }

#pragma unroll
    for (int mt = 0; mt < 4; mt++)
#pragma unroll
        for (int nt = 0; nt < 4; nt++) {
            int c0 = col0 + wn * 32 + nt * 8 + (lane & 3) * 2;
            float b0v = __ldg(bias + c0), b1v = __ldg(bias + c0 + 1);
#pragma unroll
            for (int half = 0; half < 2; half++) {
                int r = row0 + wm * 64 + mt * 16 + (lane >> 2) + half * 8;
                float v0 = acc[mt][nt][half * 2 + 0] + b0v;
                float v1 = acc[mt][nt][half * 2 + 1] + b1v;
                uint32_t h, l; split2(v0, v1, h, l);
                int bb = r >> 11, s = r & 2047, hh = c0 >> 6, d = c0 & 63;
                size_t o = (((size_t)(bb * H_NUM + hh) * S_LEN + s) << 6) + d;
                *(uint32_t*)(dh + o) = h;
                *(uint32_t*)(dl + o) = l;
            }
        }
}

// ---------------------------------------------------------------------------
// Scores (fused exp + row sums): one CTA per (g, 128-row strip).
// V (128x64 hi/lo) resident; K streamed in 64-row subtiles via cp.async
// (2-stage).  Writes probs = exp(V.K/8) unnormalized; g_rowsum = row sums.
// smem: Vh(0) Vl(18432) | Kstage[2] @36864 (18432 each: Kh 9216 + Kl 9216)
//       srow @73728 (512).  Total 74240 -> 2 CTAs/SM.
// ---------------------------------------------------------------------------
#define SC_KST 18432
__global__ void __launch_bounds__(256, 2)
scores_kernel(float* __restrict__ probs)
{
    extern __shared__ __align__(1024) char smem[];
    const uint32_t sb = smem_u32(smem);
    const int tid = threadIdx.x, lane = tid & 31, wid = tid >> 5;
    const int wm = wid & 1, wn = wid >> 1;
    const int g = blockIdx.y;
    const int i0 = blockIdx.x * 128;
    float* srow = (float*)(smem + 73728);

    const __nv_bfloat16* vh = g_vh + (((size_t)g * S_LEN + i0) << 6);
    const __nv_bfloat16* vl = g_vl + (((size_t)g * S_LEN + i0) << 6);
    const __nv_bfloat16* kh = g_kh + (((size_t)g * S_LEN) << 6);
    const __nv_bfloat16* kl = g_kl + (((size_t)g * S_LEN) << 6);
    float* Pg = probs + (size_t)g * S_LEN * S_LEN;

    // V tiles (plain LDG/STS, once)
#pragma unroll
    for (int t = 0; t < 4; t++) {
        int lin = tid + t * 256, r = lin >> 3, dq = (lin & 7) * 8;
        size_t go = ((size_t)r << 6) + dq;
        uint32_t so = (uint32_t)((r * 72 + dq) * 2);
        *(uint4*)(smem + so)         = *(const uint4*)(vh + go);
        *(uint4*)(smem + 18432 + so) = *(const uint4*)(vl + go);
    }
    if (tid < 128) srow[tid] = 0.0f;

    // K subtile cp.async: 64 rows x 64 cols hi+lo -> 2 chunks each per thread
#define SC_KISS(j, st) do {                                                   \
    int j0 = (j) * 64;                                                        \
    uint32_t base = sb + 36864 + (st) * SC_KST;                               \
    _Pragma("unroll")                                                         \
    for (int t = 0; t < 2; t++) {                                             \
        int lin = tid + t * 256, r = lin >> 3, dq = (lin & 7) * 8;            \
        uint32_t so = (uint32_t)((r * 72 + dq) * 2);                          \
        size_t go = (((size_t)(j0 + r)) << 6) + dq;                           \
        cp16(base + so,        kh + go);                                      \
        cp16(base + 9216 + so, kl + go);                                      \
    }                                                                         \
} while (0)

    float rsum[4][2];
#pragma unroll
    for (int i = 0; i < 4; i++) { rsum[i][0] = 0.0f; rsum[i][1] = 0.0f; }

    SC_KISS(0, 0); CP_COMMIT();
    SC_KISS(1, 1); CP_COMMIT();

    for (int j = 0; j < 32; j++) {
        const int st = j & 1;
        CP_WAIT1();
        __syncthreads();

        float acc[4][2][4];
#pragma unroll
        for (int i = 0; i < 4; i++)
#pragma unroll
            for (int jj = 0; jj < 2; jj++)
#pragma unroll
                for (int x = 0; x < 4; x++) acc[i][jj][x] = 0.0f;

        uint32_t kb = sb + 36864 + st * SC_KST;
        mma_n64<4, 72, 72>(acc, sb, sb + 18432, kb, kb + 9216, lane, wm, wn);

        __syncthreads();
        if (j + 2 < 32) SC_KISS(j + 2, st);
        CP_COMMIT();

        const int j0 = j * 64;
#pragma unroll
        for (int mt = 0; mt < 4; mt++)
#pragma unroll
            for (int nt = 0; nt < 2; nt++) {
                int c = j0 + wn * 16 + nt * 8 + (lane & 3) * 2;
#pragma unroll
                for (int half = 0; half < 2; half++) {
                    int r = i0 + wm * 64 + mt * 16 + (lane >> 2) + half * 8;
                    float p0 = __expf(fminf(acc[mt][nt][half * 2 + 0] * 0.125f, 80.0f));
                    float p1 = __expf(fminf(acc[mt][nt][half * 2 + 1] * 0.125f, 80.0f));
                    rsum[mt][half] += p0 + p1;
                    *(float2*)(Pg + (size_t)r * S_LEN + c) = make_float2(p0, p1);
                }
            }
    }
#undef SC_KISS

    // Row-sum reduce: quad shuffle then smem atomics (once).
#pragma unroll
    for (int mt = 0; mt < 4; mt++)
#pragma unroll
        for (int half = 0; half < 2; half++) {
            float v = rsum[mt][half];
            v += __shfl_xor_sync(0xffffffffu, v, 1);
            v += __shfl_xor_sync(0xffffffffu, v, 2);
            if ((lane & 3) == 0)
                atomicAdd(&srow[wm * 64 + mt * 16 + (lane >> 2) + half * 8], v);
        }
    __syncthreads();
    if (tid < 128) g_rowsum[(size_t)g * S_LEN + i0 + tid] = srow[tid];
}

// ---------------------------------------------------------------------------
// attn: normalize probs (writeback) + MMA with Q.  BM=128, BN=64, KC=32.
// cp.async pipeline (2-stage): PF32[2]@0 (16384 ea), Ph@32768 Pl@43008
// (10240 ea, single), Qstage[2]@53248 (9216 ea: Qh 4608 + Ql 4608),
// inv@71680 (512).  Total 72192 -> 2 CTAs/SM.
// ---------------------------------------------------------------------------
__global__ void __launch_bounds__(256, 2)
attn_kernel(float* __restrict__ probs)
{
    extern __shared__ __align__(1024) char smem[];
    const uint32_t sb = smem_u32(smem);
    const int tid = threadIdx.x, lane = tid & 31, wid = tid >> 5;
    const int wm = wid & 1, wn = wid >> 1;
    const int g = blockIdx.y;
    const int i0 = blockIdx.x * 128;
    float* Pg = probs + (size_t)g * S_LEN * S_LEN;
    const __nv_bfloat16* qh = g_qh + (((size_t)g * S_LEN) << 6);
    const __nv_bfloat16* ql = g_ql + (((size_t)g * S_LEN) << 6);
    float* inv = (float*)(smem + 71680);

    if (tid < 128)
        inv[tid] = 1.0f / g_rowsum[(size_t)g * S_LEN + i0 + tid];

    float acc[4][2][4];
#pragma unroll
    for (int i = 0; i < 4; i++)
#pragma unroll
        for (int j = 0; j < 2; j++)
#pragma unroll
            for (int x = 0; x < 4; x++) acc[i][j][x] = 0.0f;

    // issue stage: probs fp32 tile 128x32 (pitch 32 f) + Q 32x64 hi/lo
#define AT_ISS(c, st) do {                                                    \
    int k0 = (c) * 32;                                                        \
    uint32_t pbase = sb + (st) * 16384;                                       \
    _Pragma("unroll")                                                         \
    for (int t = 0; t < 4; t++) {                                             \
        int lin = tid + t * 256, r = lin >> 3, kq = (lin & 7) * 4;            \
        cp16(pbase + (uint32_t)((r * 32 + kq) * 4),                           \
             Pg + (size_t)(i0 + r) * S_LEN + k0 + kq);                        \
    }                                                                         \
    {                                                                         \
        uint32_t qbase = sb + 53248 + (st) * 9216;                            \
        int r = tid >> 3, dq = (tid & 7) * 8;                                 \
        size_t go = (((size_t)(k0 + r)) << 6) + dq;                           \
        uint32_t so = (uint32_t)((r * 72 + dq) * 2);                          \
        cp16(qbase + so,        qh + go);                                     \
        cp16(qbase + 4608 + so, ql + go);                                     \
    }                                                                         \
} while (0)

    AT_ISS(0, 0); CP_COMMIT();
    AT_ISS(1, 1); CP_COMMIT();

    for (int c = 0; c < 64; c++) {
        const int st = c & 1;
        CP_WAIT1();
        __syncthreads();

        // transform: normalize, write probs back, split to Ph/Pl
        const int k0 = c * 32;
        uint32_t pbase = sb + st * 16384;
#pragma unroll
        for (int t = 0; t < 4; t++) {
            int lin = tid + t * 256, r = lin >> 3, kq = (lin & 7) * 4;
            float4 p = *(float4*)(smem + (pbase - sb) + (r * 32 + kq) * 4);
            float iz = inv[r];
            float4 pn = {p.x * iz, p.y * iz, p.z * iz, p.w * iz};
            *(float4*)(Pg + (size_t)(i0 + r) * S_LEN + k0 + kq) = pn;
            uint32_t h0, l0, h1, l1;
            split2(pn.x, pn.y, h0, l0);
            split2(pn.z, pn.w, h1, l1);
            *(uint2*)(smem + 32768 + (r * 40 + kq) * 2) = make_uint2(h0, h1);
            *(uint2*)(smem + 43008 + (r * 40 + kq) * 2) = make_uint2(l0, l1);
        }
        __syncthreads();

        // MMA: A = Ph/Pl (pitch 40), B = Q stage (trans ldsm, pitch 72)
        uint32_t sAh = sb + 32768, sAl = sb + 43008;
        uint32_t qb  = sb + 53248 + st * 9216;
#pragma unroll
        for (int ks = 0; ks < 2; ks++) {
            uint32_t ah[4][4], al[4][4], bh[2][2], bl[2][2];
            const int arow = wm * 64 + (lane & 15);
            const int acol = ks * 16 + ((lane & 16) >> 1);
#pragma unroll
            for (int mt = 0; mt < 4; mt++) {
                uint32_t off = (uint32_t)(((arow + mt * 16) * 40 + acol) << 1);
                ldsm4(ah[mt], sAh + off);
                ldsm4(al[mt], sAl + off);
            }
            uint32_t qoff = (uint32_t)(((ks * 16 + (lane & 15)) * 72 +
                                        wn * 16 + ((lane & 16) >> 1)) << 1);
            uint32_t t4[4];
            ldsm4t(t4, qb + qoff);
            bh[0][0] = t4[0]; bh[0][1] = t4[1]; bh[1][0] = t4[2]; bh[1][1] = t4[3];
            ldsm4t(t4, qb + 4608 + qoff);
            bl[0][0] = t4[0]; bl[0][1] = t4[1]; bl[1][0] = t4[2]; bl[1][1] = t4[3];
#pragma unroll
            for (int mt = 0; mt < 4; mt++)
#pragma unroll
                for (int nt = 0; nt < 2; nt++) {
                    mma16816(acc[mt][nt], ah[mt], bh[nt]);
                    mma16816(acc[mt][nt], ah[mt], bl[nt]);
                    mma16816(acc[mt][nt], al[mt], bh[nt]);
                }
        }
        __syncthreads();
        if (c + 2 < 64) AT_ISS(c + 2, st);
        CP_COMMIT();
    }
#undef AT_ISS

    const int bb = g >> 4, hh = g & 15;
#pragma unroll
    for (int mt = 0; mt < 4; mt++)
#pragma unroll
        for (int nt = 0; nt < 2; nt++) {
            int d = wn * 16 + nt * 8 + (lane & 3) * 2;
#pragma unroll
            for (int half = 0; half < 2; half++) {
                int s = i0 + wm * 64 + mt * 16 + (lane >> 2) + half * 8;
                uint32_t h, l;
                split2(acc[mt][nt][half * 2], acc[mt][nt][half * 2 + 1], h, l);
                size_t o = ((size_t)(bb * S_LEN + s)) * E_DIM + hh * 64 + d;
                *(uint32_t*)(g_ah + o) = h;
                *(uint32_t*)(g_al + o) = l;
            }
        }
}

// ---------------------------------------------------------------------------
// Final: out = attn @ Wf + bf.  A already bf16 split.  BM=BN=128, KC=32.
// ---------------------------------------------------------------------------
__global__ void __launch_bounds__(256, 1)
final_kernel(const float* __restrict__ bf, float* __restrict__ out)
{
    extern __shared__ __align__(1024) char smem[];
    const uint32_t sb = smem_u32(smem);
    const int tid = threadIdx.x, lane = tid & 31, wid = tid >> 5;
    const int wm = wid & 1, wn = wid >> 1;
    const int row0 = blockIdx.y * 128, col0 = blockIdx.x * 128;
    const __nv_bfloat16* wth = g_wth + ((size_t)3 << 20);
    const __nv_bfloat16* wtl = g_wtl + ((size_t)3 << 20);

    float acc[4][4][4];
#pragma unroll
    for (int i = 0; i < 4; i++)
#pragma unroll
        for (int j = 0; j < 4; j++)
#pragma unroll
            for (int x = 0; x < 4; x++) acc[i][j][x] = 0.0f;

    uint4 arh[2], arl[2], brh[2], brl[2];

#define FN_LDG(c) do {                                                        \
    int k0 = (c) * 32;                                                        \
    _Pragma("unroll")                                                         \
    for (int t = 0; t < 2; t++) {                                             \
        int lin = tid + t * 256, r = lin >> 2, kq = (lin & 3) * 8;            \
        size_t ao = (size_t)(row0 + r) * E_DIM + k0 + kq;                     \
        arh[t] = *(const uint4*)(g_ah + ao);                                  \
        arl[t] = *(const uint4*)(g_al + ao);                                  \
        size_t bo = (size_t)(col0 + r) * E_DIM + k0 + kq;                     \
        brh[t] = *(const uint4*)(wth + bo);                                   \
        brl[t] = *(const uint4*)(wtl + bo);                                   \
    }                                                                         \
} while (0)

#define FN_STS(st) do {                                                       \
    char* base = smem + (st) * PJ_STAGE;                                      \
    _Pragma("unroll")                                                         \
    for (int t = 0; t < 2; t++) {                                             \
        int lin = tid + t * 256, r = lin >> 2, kq = (lin & 3) * 8;            \
        *(uint4*)(base + (r * 40 + kq) * 2)         = arh[t];                 \
        *(uint4*)(base + 10240 + (r * 40 + kq) * 2) = arl[t];                 \
        *(uint4*)(base + 20480 + (r * 40 + kq) * 2) = brh[t];                 \
        *(uint4*)(base + 30720 + (r * 40 + kq) * 2) = brl[t];                 \
    }                                                                         \
} while (0)

    FN_LDG(0); FN_STS(0); __syncthreads();
    for (int c = 0; c < 32; c++) {
        int st = c & 1;
        if (c + 1 < 32) FN_LDG(c + 1);
        uint32_t s0 = sb + st * PJ_STAGE;
        mma_block128<2, 40, 40>(acc, s0, s0 + 10240, s0 + 20480, s0 + 30720,
                                lane, wm, wn);
        if (c + 1 < 32) FN_STS(st ^ 1);
        __syncthreads();
    }
#undef FN_LDG
#undef FN_STS

#pragma unroll
    for (int mt = 0; mt < 4; mt++)
#pragma unroll
        for (int nt = 0; nt < 4; nt++) {
            int c0 = col0 + wn * 32 + nt * 8 + (lane & 3) * 2;
            float b0v = __ldg(bf + c0), b1v = __ldg(bf + c0 + 1);
#pragma unroll
            for (int half = 0; half < 2; half++) {
                int r = row0 + wm * 64 + mt * 16 + (lane >> 2) + half * 8;
                float2 o = {acc[mt][nt][half * 2] + b0v, acc[mt][nt][half * 2 + 1] + b1v};
                *(float2*)(out + (size_t)r * E_DIM + c0) = o;
            }
        }
}

// ---------------------------------------------------------------------------
extern "C" void kernel_launch(void* const* d_in, const int* in_sizes, int n_in,
                              void* d_out, int out_size)
{
    const float* query = (const float*)d_in[0];
    const float* key   = (const float*)d_in[1];
    const float* value = (const float*)d_in[2];
    const float* wq    = (const float*)d_in[3];
    const float* bq    = (const float*)d_in[4];
    const float* wk    = (const float*)d_in[5];
    const float* bk    = (const float*)d_in[6];
    const float* wv    = (const float*)d_in[7];
    const float* bv    = (const float*)d_in[8];
    const float* wf    = (const float*)d_in[9];
    const float* bf    = (const float*)d_in[10];

    float* out = (float*)d_out;
    const size_t probs_elems = (size_t)GH * S_LEN * S_LEN;
    size_t off = ((size_t)out_size > probs_elems) ? ((size_t)out_size - probs_elems) : 0;
    float* probs = out + off;

    const int SMEM_PJ = 2 * PJ_STAGE;   // 81920
    const int SMEM_SC = 74240;
    const int SMEM_AT = 72192;

    cudaFuncSetAttribute(proj_kernel,   cudaFuncAttributeMaxDynamicSharedMemorySize, SMEM_PJ);
    cudaFuncSetAttribute(scores_kernel, cudaFuncAttributeMaxDynamicSharedMemorySize, SMEM_SC);
    cudaFuncSetAttribute(attn_kernel,   cudaFuncAttributeMaxDynamicSharedMemorySize, SMEM_AT);
    cudaFuncSetAttribute(final_kernel,  cudaFuncAttributeMaxDynamicSharedMemorySize, SMEM_PJ);

    prep_w_kernel<<<dim3(32, 32, 4), dim3(32, 8)>>>(wq, wk, wv, wf);
    proj_kernel<<<dim3(8, 32, 3), 256, SMEM_PJ>>>(query, key, value, bq, bk, bv);
    scores_kernel<<<dim3(16, 32), 256, SMEM_SC>>>(probs);
    attn_kernel<<<dim3(16, 32), 256, SMEM_AT>>>(probs);
    final_kernel<<<dim3(8, 32), 256, SMEM_PJ>>>(bf, out);
}